// round 1
// baseline (speedup 1.0000x reference)
#include <cuda_runtime.h>

#define Hd 512
#define Bn 8
#define Sn 128
#define Mn 32
#define Nn 64

// Scratch (no allocations allowed; __device__ globals)
__device__ float g_scores[Bn * Sn * Mn];          // 32768
__device__ float g_pooled[Bn * Sn * Hd];          // 524288
__device__ float g_ci[Bn * (Sn - 1) * Hd];        // 520192

// ---- packed fp32x2 helpers (Blackwell FFMA2, PTX-only path) ----
__device__ __forceinline__ void ffma2(unsigned long long& c,
                                      unsigned long long a,
                                      unsigned long long b) {
    asm("fma.rn.f32x2 %0, %1, %2, %0;" : "+l"(c) : "l"(a), "l"(b));
}
__device__ __forceinline__ float2 unpack2(unsigned long long v) {
    unsigned int lo, hi;
    asm("mov.b64 {%0, %1}, %2;" : "=r"(lo), "=r"(hi) : "l"(v));
    return make_float2(__uint_as_float(lo), __uint_as_float(hi));
}

// ============================================================================
// Kernel 1: scores[b,s,m] = sum_g tanh( (x@Wa1)[g] + ba1[g] ) * wa2[g]
// One block per (b,s): BM=32 rows x BN=512 cols, K=512.
// Thread grid (tm 0..3, tg 0..63); each thread: 8 rows x 4 col-pairs.
// ============================================================================
__global__ __launch_bounds__(256) void k_scores(
    const float* __restrict__ x, const float* __restrict__ Wa1,
    const float* __restrict__ ba1, const float* __restrict__ wa2)
{
    const int bs = blockIdx.x;
    const int tid = threadIdx.x;
    const int tg = tid & 63;
    const int tm = tid >> 6;

    __shared__ __align__(16) float2 As2[16][32];   // A duplicated pairs, [k][m]
    __shared__ __align__(16) float  Bs[16][512];   // [k][g]
    __shared__ float red[32][64];

    unsigned long long acc[8][4];
#pragma unroll
    for (int i = 0; i < 8; i++)
#pragma unroll
        for (int j = 0; j < 4; j++) acc[i][j] = 0ull;

    const float* xrow = x + (size_t)bs * Mn * Hd;

    for (int kk = 0; kk < Hd; kk += 16) {
        if (tid < 128) {
            int m = tid >> 2, k4 = (tid & 3) * 4;
            float4 v = *(const float4*)(xrow + (size_t)m * Hd + kk + k4);
            As2[k4 + 0][m] = make_float2(v.x, v.x);
            As2[k4 + 1][m] = make_float2(v.y, v.y);
            As2[k4 + 2][m] = make_float2(v.z, v.z);
            As2[k4 + 3][m] = make_float2(v.w, v.w);
        }
#pragma unroll
        for (int q = 0; q < 8; q++) {
            int f = tid + 256 * q;
            int k = f >> 7, g4 = (f & 127) * 4;
            *(float4*)&Bs[k][g4] = *(const float4*)(Wa1 + (size_t)(kk + k) * Hd + g4);
        }
        __syncthreads();
#pragma unroll
        for (int k = 0; k < 16; k++) {
            unsigned long long a2[8], b2[4];
#pragma unroll
            for (int i = 0; i < 8; i++)
                a2[i] = *(const unsigned long long*)&As2[k][tm + 4 * i];
#pragma unroll
            for (int j = 0; j < 4; j++)
                b2[j] = *(const unsigned long long*)&Bs[k][2 * tg + 128 * j];
#pragma unroll
            for (int i = 0; i < 8; i++)
#pragma unroll
                for (int j = 0; j < 4; j++) ffma2(acc[i][j], a2[i], b2[j]);
        }
        __syncthreads();
    }

    // epilogue: tanh + dot with wa2, reduce over the 512 g columns
    float part[8];
#pragma unroll
    for (int i = 0; i < 8; i++) {
        float s = 0.f;
#pragma unroll
        for (int j = 0; j < 4; j++) {
            int g = 2 * tg + 128 * j;
            float2 p = unpack2(acc[i][j]);
            s += tanhf(p.x + ba1[g]) * wa2[g];
            s += tanhf(p.y + ba1[g + 1]) * wa2[g + 1];
        }
        part[i] = s;
    }
#pragma unroll
    for (int i = 0; i < 8; i++) red[tm + 4 * i][tg] = part[i];
    __syncthreads();
    if (tid < 32) {
        float s = 0.f;
#pragma unroll
        for (int t = 0; t < 64; t++) s += red[tid][t];
        g_scores[bs * Mn + tid] = s;
    }
}

// ============================================================================
// Kernel 2: softmax over m (=32) + pooled[b,s,h] = sum_m attn[m]*x[b,s,m,h]
// ============================================================================
__global__ __launch_bounds__(256) void k_pool(const float* __restrict__ x)
{
    const int bs = blockIdx.x;
    __shared__ float attn[32];
    const int tid = threadIdx.x;
    if (tid < 32) {
        float s = g_scores[bs * Mn + tid];
        float mx = s;
#pragma unroll
        for (int o = 16; o > 0; o >>= 1)
            mx = fmaxf(mx, __shfl_xor_sync(0xffffffffu, mx, o));
        float e = expf(s - mx);
        float sum = e;
#pragma unroll
        for (int o = 16; o > 0; o >>= 1)
            sum += __shfl_xor_sync(0xffffffffu, sum, o);
        attn[tid] = e / sum;
    }
    __syncthreads();
    const float* xb = x + (size_t)bs * Mn * Hd;
    for (int h = tid; h < Hd; h += 256) {
        float s = 0.f;
#pragma unroll
        for (int m = 0; m < Mn; m++) s = fmaf(attn[m], xb[(size_t)m * Hd + h], s);
        g_pooled[(size_t)bs * Hd + h] = s;
    }
}

// ============================================================================
// Kernel 3: ci[b,s',g] = sum_h pooled[b,s',h] * Wl[g, Hd+h] + bl[g]   (s'<127)
// Block = (b, 32-row tile). BM=32 x BN=512, K=512.
// ============================================================================
__global__ __launch_bounds__(256) void k_ci(
    const float* __restrict__ Wl, const float* __restrict__ bl)
{
    const int b = blockIdx.x >> 2;
    const int s0 = (blockIdx.x & 3) * 32;
    const int tid = threadIdx.x;
    const int tg = tid & 63;
    const int tm = tid >> 6;

    __shared__ __align__(16) float2 As2[16][32];
    __shared__ __align__(16) float  Bs[16][516];   // padded rows (store conflicts)

    unsigned long long acc[8][4];
#pragma unroll
    for (int i = 0; i < 8; i++)
#pragma unroll
        for (int j = 0; j < 4; j++) acc[i][j] = 0ull;

    for (int kk = 0; kk < Hd; kk += 16) {
        if (tid < 128) {
            int m = tid >> 2, k4 = (tid & 3) * 4;
            int sp = s0 + m;
            float4 v = make_float4(0.f, 0.f, 0.f, 0.f);
            if (sp < 127)
                v = *(const float4*)(g_pooled + ((size_t)b * Sn + sp) * Hd + kk + k4);
            As2[k4 + 0][m] = make_float2(v.x, v.x);
            As2[k4 + 1][m] = make_float2(v.y, v.y);
            As2[k4 + 2][m] = make_float2(v.z, v.z);
            As2[k4 + 3][m] = make_float2(v.w, v.w);
        }
#pragma unroll
        for (int q = 0; q < 8; q++) {
            int f = tid + 256 * q;
            int g = f >> 2, k4 = (f & 3) * 4;
            float4 v = *(const float4*)(Wl + (size_t)g * (2 * Hd) + Hd + kk + k4);
            Bs[k4 + 0][g] = v.x;
            Bs[k4 + 1][g] = v.y;
            Bs[k4 + 2][g] = v.z;
            Bs[k4 + 3][g] = v.w;
        }
        __syncthreads();
#pragma unroll
        for (int k = 0; k < 16; k++) {
            unsigned long long a2[8], b2[4];
#pragma unroll
            for (int i = 0; i < 8; i++)
                a2[i] = *(const unsigned long long*)&As2[k][tm + 4 * i];
#pragma unroll
            for (int j = 0; j < 4; j++)
                b2[j] = *(const unsigned long long*)&Bs[k][2 * tg + 128 * j];
#pragma unroll
            for (int i = 0; i < 8; i++)
#pragma unroll
                for (int j = 0; j < 4; j++) ffma2(acc[i][j], a2[i], b2[j]);
        }
        __syncthreads();
    }

#pragma unroll
    for (int i = 0; i < 8; i++) {
        int sp = s0 + tm + 4 * i;
        if (sp < 127) {
            float* crow = g_ci + ((size_t)b * 127 + sp) * Hd;
#pragma unroll
            for (int j = 0; j < 4; j++) {
                int g = 2 * tg + 128 * j;
                float2 p = unpack2(acc[i][j]);
                crow[g]     = p.x + bl[g];
                crow[g + 1] = p.y + bl[g + 1];
            }
        }
    }
}

// ============================================================================
// Kernel 4: pre = y[b,s'+1] @ Wy^T + ci ; out = y + i_x * sigmoid(pre)
// Block = (b*127+s', g-half). BM=64 (= n dim exactly) x BN=256, K=512.
// Thread grid (tm 0..7, tg 0..31); each thread 8 rows x 4 col-pairs.
// ============================================================================
__global__ __launch_bounds__(256) void k_main(
    const float* __restrict__ y, const float* __restrict__ Wl,
    float* __restrict__ out)
{
    const int bsp = blockIdx.x;       // 0..1015
    const int b = bsp / 127;
    const int sp = bsp % 127;
    const int gg = blockIdx.y * 256;
    const int tid = threadIdx.x;
    const int tg = tid & 31;
    const int tm = tid >> 5;

    __shared__ __align__(16) float2 As2[16][64];
    __shared__ __align__(16) float  Bs[16][260];

    unsigned long long acc[8][4];
#pragma unroll
    for (int i = 0; i < 8; i++)
#pragma unroll
        for (int j = 0; j < 4; j++) acc[i][j] = 0ull;

    const float* yrow = y + (size_t)((b * Sn) + sp + 1) * Nn * Hd;

    for (int kk = 0; kk < Hd; kk += 16) {
        {
            int m = tid >> 2, k4 = (tid & 3) * 4;
            float4 v = *(const float4*)(yrow + (size_t)m * Hd + kk + k4);
            As2[k4 + 0][m] = make_float2(v.x, v.x);
            As2[k4 + 1][m] = make_float2(v.y, v.y);
            As2[k4 + 2][m] = make_float2(v.z, v.z);
            As2[k4 + 3][m] = make_float2(v.w, v.w);
        }
#pragma unroll
        for (int q = 0; q < 4; q++) {
            int f = tid + 256 * q;
            int gl = f >> 2, k4 = (f & 3) * 4;
            float4 v = *(const float4*)(Wl + (size_t)(gg + gl) * (2 * Hd) + kk + k4);
            Bs[k4 + 0][gl] = v.x;
            Bs[k4 + 1][gl] = v.y;
            Bs[k4 + 2][gl] = v.z;
            Bs[k4 + 3][gl] = v.w;
        }
        __syncthreads();
#pragma unroll
        for (int k = 0; k < 16; k++) {
            unsigned long long a2[8], b2[4];
#pragma unroll
            for (int i = 0; i < 8; i++)
                a2[i] = *(const unsigned long long*)&As2[k][tm + 8 * i];
#pragma unroll
            for (int j = 0; j < 4; j++)
                b2[j] = *(const unsigned long long*)&Bs[k][2 * tg + 64 * j];
#pragma unroll
            for (int i = 0; i < 8; i++)
#pragma unroll
                for (int j = 0; j < 4; j++) ffma2(acc[i][j], a2[i], b2[j]);
        }
        __syncthreads();
    }

    const float* cir = g_ci + ((size_t)b * 127 + sp) * Hd + gg;
    const float* ixr = g_pooled + ((size_t)(b * Sn) + sp) * Hd + gg;
    float* orow = out + (size_t)((b * Sn) + sp + 1) * Nn * Hd;

#pragma unroll
    for (int i = 0; i < 8; i++) {
        int n = tm + 8 * i;
#pragma unroll
        for (int j = 0; j < 4; j++) {
            int gl = 2 * tg + 64 * j;
            float2 p = unpack2(acc[i][j]);
            float pre0 = p.x + cir[gl];
            float pre1 = p.y + cir[gl + 1];
            float gt0 = 1.f / (1.f + expf(-pre0));
            float gt1 = 1.f / (1.f + expf(-pre1));
            float2 yv = *(const float2*)(yrow + (size_t)n * Hd + gg + gl);
            float2 o;
            o.x = yv.x + ixr[gl] * gt0;
            o.y = yv.y + ixr[gl + 1] * gt1;
            *(float2*)(orow + (size_t)n * Hd + gg + gl) = o;
        }
    }
}

// ============================================================================
// Kernel 5: out[:, 0] = y[:, 0]
// ============================================================================
__global__ __launch_bounds__(256) void k_copy0(
    const float* __restrict__ y, float* __restrict__ out)
{
    const int b = blockIdx.y;
    const int i = (blockIdx.x * 256 + threadIdx.x) * 4;   // float4 index
    const size_t base = (size_t)b * Sn * Nn * Hd;
    if (i < Nn * Hd)
        *(float4*)(out + base + i) = *(const float4*)(y + base + i);
}

extern "C" void kernel_launch(void* const* d_in, const int* in_sizes, int n_in,
                              void* d_out, int out_size)
{
    const float* x   = (const float*)d_in[0];
    const float* y   = (const float*)d_in[1];
    const float* Wa1 = (const float*)d_in[2];
    const float* ba1 = (const float*)d_in[3];
    const float* wa2 = (const float*)d_in[4];
    const float* Wl  = (const float*)d_in[5];
    const float* bl  = (const float*)d_in[6];
    float* out = (float*)d_out;

    k_scores<<<Bn * Sn, 256>>>(x, Wa1, ba1, wa2);
    k_pool<<<Bn * Sn, 256>>>(x);
    k_ci<<<Bn * 4, 256>>>(Wl, bl);
    k_main<<<dim3(Bn * (Sn - 1), 2), 256>>>(y, Wl, out);
    k_copy0<<<dim3((Nn * Hd / 4 + 255) / 256, Bn), 256>>>(y, out);
}

// round 4
// speedup vs baseline: 2.5474x; 2.5474x over previous
#include <cuda_runtime.h>
#include <cuda_bf16.h>
#include <cstdint>

#define Hd 512
#define Bn 8
#define Sn 128
#define Mn 32
#define Nn 64

#define ROWS_Y  (Bn * (Sn - 1) * Nn)   // 65024 = 508*128
#define ROWS_X  (Bn * Sn * Mn)         // 32768 = 256*128
#define NSLICE  16

// ---------------- device scratch ----------------
__device__ float g_spart[NSLICE * ROWS_X];
__device__ float g_pooled[Bn * Sn * Hd];
__device__ float g_ci[Bn * (Sn - 1) * Hd];

__device__ __nv_bfloat16 g_xhi[(size_t)ROWS_X * Hd];
__device__ __nv_bfloat16 g_xlo[(size_t)ROWS_X * Hd];
__device__ __nv_bfloat16 g_yhi[(size_t)ROWS_Y * Hd];
__device__ __nv_bfloat16 g_ylo[(size_t)ROWS_Y * Hd];
__device__ __nv_bfloat16 g_bshi[Hd * Hd];   // scores B: Wa1^T, [g][k]
__device__ __nv_bfloat16 g_bslo[Hd * Hd];
__device__ __nv_bfloat16 g_bmhi[Hd * Hd];   // main B: Wy rows, [g][k]
__device__ __nv_bfloat16 g_bmlo[Hd * Hd];

// ---------------- helpers ----------------
__device__ __forceinline__ uint32_t smem_u32(const void* p) {
    uint32_t a;
    asm("{ .reg .u64 t; cvta.to.shared.u64 t, %1; cvt.u32.u64 %0, t; }" : "=r"(a) : "l"(p));
    return a;
}
__device__ __forceinline__ void cp16(uint32_t saddr, const void* gptr) {
    asm volatile("cp.async.cg.shared.global [%0], [%1], 16;" :: "r"(saddr), "l"(gptr));
}
__device__ __forceinline__ void cp_commit_wait() {
    asm volatile("cp.async.commit_group;");
    asm volatile("cp.async.wait_group 0;" ::: "memory");
}
__device__ __forceinline__ void ldsm4(uint32_t* r, uint32_t addr) {
    asm volatile("ldmatrix.sync.aligned.m8n8.x4.shared.b16 {%0,%1,%2,%3}, [%4];"
                 : "=r"(r[0]), "=r"(r[1]), "=r"(r[2]), "=r"(r[3]) : "r"(addr));
}
__device__ __forceinline__ void mma16816(float* c, const uint32_t* a, const uint32_t* b) {
    asm volatile(
        "mma.sync.aligned.m16n8k16.row.col.f32.bf16.bf16.f32 "
        "{%0,%1,%2,%3}, {%4,%5,%6,%7}, {%8,%9}, {%0,%1,%2,%3};"
        : "+f"(c[0]), "+f"(c[1]), "+f"(c[2]), "+f"(c[3])
        : "r"(a[0]), "r"(a[1]), "r"(a[2]), "r"(a[3]), "r"(b[0]), "r"(b[1]));
}
__device__ __forceinline__ float fsig(float x)  { return __fdividef(1.f, 1.f + __expf(-x)); }
__device__ __forceinline__ float ftanh(float x) { return 1.f - __fdividef(2.f, __expf(2.f * x) + 1.f); }

// fp32x2 (k_ci)
__device__ __forceinline__ void ffma2(unsigned long long& c, unsigned long long a, unsigned long long b) {
    asm("fma.rn.f32x2 %0, %1, %2, %0;" : "+l"(c) : "l"(a), "l"(b));
}
__device__ __forceinline__ float2 unpack2(unsigned long long v) {
    unsigned int lo, hi;
    asm("mov.b64 {%0, %1}, %2;" : "=r"(lo), "=r"(hi) : "l"(v));
    return make_float2(__uint_as_float(lo), __uint_as_float(hi));
}

// bf16 split helpers
__device__ __forceinline__ unsigned pk(float a, float b) {
    __nv_bfloat162 t = __floats2bfloat162_rn(a, b);
    return *reinterpret_cast<unsigned*>(&t);
}
__device__ __forceinline__ float rb(float a) { return __bfloat162float(__float2bfloat16_rn(a)); }

// swizzled offset inside a [rows x 64 bf16] tile (128 B rows)
__device__ __forceinline__ uint32_t sw(int row, int c8) {
    return (uint32_t)(row * 128 + ((c8 ^ (row & 7)) << 4));
}

// ============================================================================
// Conversion kernels
// ============================================================================
__global__ __launch_bounds__(128) void k_cvt_x(const float* __restrict__ x) {
    const int r = blockIdx.x;
    const int t = threadIdx.x;
    float4 v = *(const float4*)(x + ((size_t)r << 9) + t * 4);
    uint2 h, l;
    h.x = pk(v.x, v.y); h.y = pk(v.z, v.w);
    l.x = pk(v.x - rb(v.x), v.y - rb(v.y));
    l.y = pk(v.z - rb(v.z), v.w - rb(v.w));
    ((uint2*)g_xhi)[(size_t)r * 128 + t] = h;
    ((uint2*)g_xlo)[(size_t)r * 128 + t] = l;
}

__global__ __launch_bounds__(128) void k_cvt_y(const float* __restrict__ y) {
    const int r = blockIdx.x;                // compact row in [0, 65024)
    const int t = threadIdx.x;
    const int b = r / (127 * Nn);
    const int rem = r - b * (127 * Nn);
    const int sp = rem >> 6, n = rem & 63;
    const float* src = y + ((((size_t)(b * Sn) + sp + 1) * Nn + n) << 9) + t * 4;
    float4 v = *(const float4*)src;
    uint2 h, l;
    h.x = pk(v.x, v.y); h.y = pk(v.z, v.w);
    l.x = pk(v.x - rb(v.x), v.y - rb(v.y));
    l.y = pk(v.z - rb(v.z), v.w - rb(v.w));
    ((uint2*)g_yhi)[(size_t)r * 128 + t] = h;
    ((uint2*)g_ylo)[(size_t)r * 128 + t] = l;
}

__global__ __launch_bounds__(128) void k_cvt_w(const float* __restrict__ Wa1,
                                               const float* __restrict__ Wl) {
    const int g = blockIdx.x;
    const int t = threadIdx.x;
    {   // g_bm[g][k] = Wl[g*1024 + k]  (Wy row)
        float4 v = *(const float4*)(Wl + (size_t)g * 1024 + t * 4);
        uint2 h, l;
        h.x = pk(v.x, v.y); h.y = pk(v.z, v.w);
        l.x = pk(v.x - rb(v.x), v.y - rb(v.y));
        l.y = pk(v.z - rb(v.z), v.w - rb(v.w));
        ((uint2*)g_bmhi)[(size_t)g * 128 + t] = h;
        ((uint2*)g_bmlo)[(size_t)g * 128 + t] = l;
    }
    {   // g_bs[g][k] = Wa1[k*512 + g]  (transpose)
        int k0 = t * 4;
        float a = Wa1[(size_t)(k0 + 0) * Hd + g];
        float b = Wa1[(size_t)(k0 + 1) * Hd + g];
        float c = Wa1[(size_t)(k0 + 2) * Hd + g];
        float d = Wa1[(size_t)(k0 + 3) * Hd + g];
        uint2 h, l;
        h.x = pk(a, b); h.y = pk(c, d);
        l.x = pk(a - rb(a), b - rb(b));
        l.y = pk(c - rb(c), d - rb(d));
        ((uint2*)g_bshi)[(size_t)g * 128 + t] = h;
        ((uint2*)g_bslo)[(size_t)g * 128 + t] = l;
    }
}

// ============================================================================
// Shared HMMA mainloop: block tile 128(M) x 128(N), K=512 in 64-chunks.
// smem stage: Ahi 16K | Alo 16K | Bhi 16K | Blo 16K = 64 KB.
// Warp grid 2(M) x 4(N), warp tile 64x32. 3-term bf16 split into fp32 acc.
// ============================================================================
#define DSMEM (65536 + 128)

__device__ __forceinline__ void hmma_mainloop(
    const __nv_bfloat16* __restrict__ Ah, const __nv_bfloat16* __restrict__ Al,
    const __nv_bfloat16* __restrict__ Bh, const __nv_bfloat16* __restrict__ Bl,
    uint32_t smu, float acc[4][4][4])
{
    const int tid = threadIdx.x;
    const int lid = tid & 31, wid = tid >> 5;
    const int wm = wid >> 2, wn = wid & 3;

    const uint32_t sA  = smu;
    const uint32_t sAl = smu + 16384;
    const uint32_t sB  = smu + 32768;
    const uint32_t sBl = smu + 49152;

    // per-thread store slots (4 chunks per array)
    int srow[4], sc8[4];
    uint32_t soff[4];
#pragma unroll
    for (int i = 0; i < 4; i++) {
        int id = tid + 256 * i;
        srow[i] = id >> 3; sc8[i] = id & 7;
        soff[i] = sw(srow[i], sc8[i]);
    }

    // ldmatrix addresses (constant across k-iters except ks term)
    const int rowA_base = wm * 64 + (lid & 15);
    const int c8A_half = lid >> 4;
    const int rowB_base = wn * 32 + ((lid >> 4) << 3) + (lid & 7);
    const int c8B_half = (lid >> 3) & 1;

    for (int kk = 0; kk < Hd; kk += 64) {
        __syncthreads();
#pragma unroll
        for (int i = 0; i < 4; i++) {
            const size_t go = (size_t)srow[i] * Hd + kk + sc8[i] * 8;
            cp16(sA  + soff[i], Ah + go);
            cp16(sAl + soff[i], Al + go);
            cp16(sB  + soff[i], Bh + go);
            cp16(sBl + soff[i], Bl + go);
        }
        cp_commit_wait();
        __syncthreads();

#pragma unroll
        for (int ks = 0; ks < 4; ks++) {
            // B fragments: 2 x ldmatrix.x4 per term (covers 4 n8-frags x k16)
            uint32_t bh[8], bl8[8];
#pragma unroll
            for (int q = 0; q < 2; q++) {
                int rowB = rowB_base + q * 16;
                int c8 = ks * 2 + c8B_half;
                uint32_t off = sw(rowB, c8);
                ldsm4(&bh[q * 4], sB + off);
                ldsm4(&bl8[q * 4], sBl + off);
            }
#pragma unroll
            for (int mf = 0; mf < 4; mf++) {
                int rowA = rowA_base + mf * 16;
                int c8 = ks * 2 + c8A_half;
                uint32_t off = sw(rowA, c8);
                uint32_t ah[4], al4[4];
                ldsm4(ah, sA + off);
                ldsm4(al4, sAl + off);
#pragma unroll
                for (int nf = 0; nf < 4; nf++) {
                    mma16816(acc[mf][nf], ah, &bh[nf * 2]);
                    mma16816(acc[mf][nf], ah, &bl8[nf * 2]);
                    mma16816(acc[mf][nf], al4, &bh[nf * 2]);
                }
            }
        }
    }
}

// ============================================================================
// k_scores_mma: pre = x@Wa1 (+ba1); partial scores = sum_g tanh(pre)*wa2
// grid (256, 4), 256 threads
// ============================================================================
__global__ __launch_bounds__(256, 2) void k_scores_mma(
    const float* __restrict__ ba1, const float* __restrict__ wa2)
{
    extern __shared__ char dyn[];
    const uint32_t smu = (smem_u32(dyn) + 127) & ~127u;

    const int row0 = blockIdx.x * 128;
    const int gg = blockIdx.y * 128;
    const int tid = threadIdx.x;
    const int lid = tid & 31, wid = tid >> 5;
    const int wm = wid >> 2, wn = wid & 3;
    const int groupID = lid >> 2, tig = lid & 3;

    float acc[4][4][4];
#pragma unroll
    for (int a = 0; a < 4; a++)
#pragma unroll
        for (int b = 0; b < 4; b++)
#pragma unroll
            for (int c = 0; c < 4; c++) acc[a][b][c] = 0.f;

    hmma_mainloop(g_xhi + ((size_t)row0 << 9), g_xlo + ((size_t)row0 << 9),
                  g_bshi + ((size_t)gg << 9),  g_bslo + ((size_t)gg << 9),
                  smu, acc);

    const int colw = gg + wn * 32;
#pragma unroll
    for (int mf = 0; mf < 4; mf++) {
#pragma unroll
        for (int half = 0; half < 2; half++) {
            const int R = row0 + wm * 64 + mf * 16 + groupID + half * 8;
            float s = 0.f;
#pragma unroll
            for (int nf = 0; nf < 4; nf++) {
                const int g = colw + nf * 8 + tig * 2;
                float a0 = acc[mf][nf][half * 2 + 0];
                float a1 = acc[mf][nf][half * 2 + 1];
                s += ftanh(a0 + __ldg(ba1 + g))     * __ldg(wa2 + g);
                s += ftanh(a1 + __ldg(ba1 + g + 1)) * __ldg(wa2 + g + 1);
            }
            s += __shfl_xor_sync(0xffffffffu, s, 1);
            s += __shfl_xor_sync(0xffffffffu, s, 2);
            if (tig == 0)
                g_spart[(blockIdx.y * 4 + wn) * ROWS_X + R] = s;
        }
    }
}

// ============================================================================
// k_main_mma: pre = y@Wy^T + ci ; out = y + i_x*sigmoid(pre)
// grid (508, 4), 256 threads
// ============================================================================
__global__ __launch_bounds__(256, 2) void k_main_mma(
    const float* __restrict__ y, float* __restrict__ out)
{
    extern __shared__ char dyn[];
    const uint32_t smu = (smem_u32(dyn) + 127) & ~127u;

    const int row0 = blockIdx.x * 128;
    const int gg = blockIdx.y * 128;
    const int tid = threadIdx.x;
    const int lid = tid & 31, wid = tid >> 5;
    const int wm = wid >> 2, wn = wid & 3;
    const int groupID = lid >> 2, tig = lid & 3;

    float acc[4][4][4];
#pragma unroll
    for (int a = 0; a < 4; a++)
#pragma unroll
        for (int b = 0; b < 4; b++)
#pragma unroll
            for (int c = 0; c < 4; c++) acc[a][b][c] = 0.f;

    hmma_mainloop(g_yhi + ((size_t)row0 << 9), g_ylo + ((size_t)row0 << 9),
                  g_bmhi + ((size_t)gg << 9),  g_bmlo + ((size_t)gg << 9),
                  smu, acc);

    const int colw = gg + wn * 32;
#pragma unroll
    for (int mf = 0; mf < 4; mf++) {
#pragma unroll
        for (int half = 0; half < 2; half++) {
            const int R = row0 + wm * 64 + mf * 16 + groupID + half * 8;
            const int b = R / 8128;
            const int rem = R - b * 8128;
            const int sp = rem >> 6, n = rem & 63;
            const size_t ybase = ((((size_t)(b * Sn) + sp + 1) * Nn + n) << 9) + colw;
            const float* cib = g_ci + (((size_t)(b * 127 + sp)) << 9) + colw;
            const float* ixb = g_pooled + (((size_t)(b * Sn) + sp) << 9) + colw;
#pragma unroll
            for (int nf = 0; nf < 4; nf++) {
                const int c = nf * 8 + tig * 2;
                float a0 = acc[mf][nf][half * 2 + 0];
                float a1 = acc[mf][nf][half * 2 + 1];
                float2 ci2 = *(const float2*)(cib + c);
                float2 ix2 = *(const float2*)(ixb + c);
                float2 y2  = *(const float2*)(y + ybase + c);
                float2 o;
                o.x = y2.x + ix2.x * fsig(a0 + ci2.x);
                o.y = y2.y + ix2.y * fsig(a1 + ci2.y);
                *(float2*)(out + ybase + c) = o;
            }
        }
    }
}

// ============================================================================
// k_pool: softmax over m + weighted pool (sums 16 score partials)
// ============================================================================
__global__ __launch_bounds__(256) void k_pool(const float* __restrict__ x)
{
    const int bs = blockIdx.x;
    __shared__ float attn[32];
    const int tid = threadIdx.x;
    if (tid < 32) {
        float s = 0.f;
#pragma unroll
        for (int q = 0; q < NSLICE; q++) s += g_spart[q * ROWS_X + bs * Mn + tid];
        float mx = s;
#pragma unroll
        for (int o = 16; o > 0; o >>= 1)
            mx = fmaxf(mx, __shfl_xor_sync(0xffffffffu, mx, o));
        float e = expf(s - mx);
        float sum = e;
#pragma unroll
        for (int o = 16; o > 0; o >>= 1)
            sum += __shfl_xor_sync(0xffffffffu, sum, o);
        attn[tid] = e / sum;
    }
    __syncthreads();
    const float* xb = x + (size_t)bs * Mn * Hd;
    for (int h = tid; h < Hd; h += 256) {
        float s = 0.f;
#pragma unroll
        for (int m = 0; m < Mn; m++) s = fmaf(attn[m], xb[(size_t)m * Hd + h], s);
        g_pooled[(size_t)bs * Hd + h] = s;
    }
}

// ============================================================================
// k_ci (FFMA2): ci = pooled @ Wi^T + bl
// ============================================================================
__global__ __launch_bounds__(256) void k_ci(
    const float* __restrict__ Wl, const float* __restrict__ bl)
{
    const int b = blockIdx.x >> 2;
    const int s0 = (blockIdx.x & 3) * 32;
    const int tid = threadIdx.x;
    const int tg = tid & 63;
    const int tm = tid >> 6;

    __shared__ __align__(16) float2 As2[16][32];
    __shared__ __align__(16) float  Bs[16][516];

    unsigned long long acc[8][4];
#pragma unroll
    for (int i = 0; i < 8; i++)
#pragma unroll
        for (int j = 0; j < 4; j++) acc[i][j] = 0ull;

    for (int kk = 0; kk < Hd; kk += 16) {
        if (tid < 128) {
            int m = tid >> 2, k4 = (tid & 3) * 4;
            int sp = s0 + m;
            float4 v = make_float4(0.f, 0.f, 0.f, 0.f);
            if (sp < 127)
                v = *(const float4*)(g_pooled + ((size_t)b * Sn + sp) * Hd + kk + k4);
            As2[k4 + 0][m] = make_float2(v.x, v.x);
            As2[k4 + 1][m] = make_float2(v.y, v.y);
            As2[k4 + 2][m] = make_float2(v.z, v.z);
            As2[k4 + 3][m] = make_float2(v.w, v.w);
        }
#pragma unroll
        for (int q = 0; q < 8; q++) {
            int f = tid + 256 * q;
            int g = f >> 2, k4 = (f & 3) * 4;
            float4 v = *(const float4*)(Wl + (size_t)g * (2 * Hd) + Hd + kk + k4);
            Bs[k4 + 0][g] = v.x;
            Bs[k4 + 1][g] = v.y;
            Bs[k4 + 2][g] = v.z;
            Bs[k4 + 3][g] = v.w;
        }
        __syncthreads();
#pragma unroll
        for (int k = 0; k < 16; k++) {
            unsigned long long a2[8], b2[4];
#pragma unroll
            for (int i = 0; i < 8; i++)
                a2[i] = *(const unsigned long long*)&As2[k][tm + 4 * i];
#pragma unroll
            for (int j = 0; j < 4; j++)
                b2[j] = *(const unsigned long long*)&Bs[k][2 * tg + 128 * j];
#pragma unroll
            for (int i = 0; i < 8; i++)
#pragma unroll
                for (int j = 0; j < 4; j++) ffma2(acc[i][j], a2[i], b2[j]);
        }
        __syncthreads();
    }

#pragma unroll
    for (int i = 0; i < 8; i++) {
        int sp = s0 + tm + 4 * i;
        if (sp < 127) {
            float* crow = g_ci + ((size_t)b * 127 + sp) * Hd;
#pragma unroll
            for (int j = 0; j < 4; j++) {
                int g = 2 * tg + 128 * j;
                float2 p = unpack2(acc[i][j]);
                crow[g]     = p.x + bl[g];
                crow[g + 1] = p.y + bl[g + 1];
            }
        }
    }
}

// ============================================================================
// k_copy0: out[:, 0] = y[:, 0]
// ============================================================================
__global__ __launch_bounds__(256) void k_copy0(
    const float* __restrict__ y, float* __restrict__ out)
{
    const int b = blockIdx.y;
    const int i = (blockIdx.x * 256 + threadIdx.x) * 4;
    const size_t base = (size_t)b * Sn * Nn * Hd;
    if (i < Nn * Hd)
        *(float4*)(out + base + i) = *(const float4*)(y + base + i);
}

extern "C" void kernel_launch(void* const* d_in, const int* in_sizes, int n_in,
                              void* d_out, int out_size)
{
    const float* x   = (const float*)d_in[0];
    const float* y   = (const float*)d_in[1];
    const float* Wa1 = (const float*)d_in[2];
    const float* ba1 = (const float*)d_in[3];
    const float* wa2 = (const float*)d_in[4];
    const float* Wl  = (const float*)d_in[5];
    const float* bl  = (const float*)d_in[6];
    float* out = (float*)d_out;

    cudaFuncSetAttribute(k_scores_mma, cudaFuncAttributeMaxDynamicSharedMemorySize, DSMEM);
    cudaFuncSetAttribute(k_main_mma,   cudaFuncAttributeMaxDynamicSharedMemorySize, DSMEM);

    k_cvt_w<<<Hd, 128>>>(Wa1, Wl);
    k_cvt_x<<<ROWS_X, 128>>>(x);
    k_cvt_y<<<ROWS_Y, 128>>>(y);
    k_scores_mma<<<dim3(ROWS_X / 128, 4), 256, DSMEM>>>(ba1, wa2);
    k_pool<<<Bn * Sn, 256>>>(x);
    k_ci<<<Bn * 4, 256>>>(Wl, bl);
    k_main_mma<<<dim3(ROWS_Y / 128, 4), 256, DSMEM>>>(y, out);
    k_copy0<<<dim3((Nn * Hd / 4 + 255) / 256, Bn), 256>>>(y, out);
}

// round 5
// speedup vs baseline: 2.8509x; 1.1191x over previous
#include <cuda_runtime.h>
#include <cuda_bf16.h>
#include <cuda_fp16.h>
#include <cstdint>

#define Hd 512
#define Bn 8
#define Sn 128
#define Mn 32
#define Nn 64

#define ROWS_Y  (Bn * (Sn - 1) * Nn)   // 65024 = 254*256
#define ROWS_X  (Bn * Sn * Mn)         // 32768 = 128*256
#define NSLICE  16

// ---------------- device scratch ----------------
__device__ float g_spart[NSLICE * ROWS_X];
__device__ float g_pooled[Bn * Sn * Hd];
__device__ float g_ci[Bn * (Sn - 1) * Hd];

__device__ __half        g_x16[(size_t)ROWS_X * Hd];
__device__ __nv_bfloat16 g_x8 [(size_t)ROWS_X * Hd];
__device__ __half        g_y16[(size_t)ROWS_Y * Hd];
__device__ __nv_bfloat16 g_y8 [(size_t)ROWS_Y * Hd];
__device__ __half        g_bs16[Hd * Hd];   // scores B: fp16(Wa1^T) [g][k]
__device__ __nv_bfloat16 g_bs8 [Hd * Hd];   // bf16 residual
__device__ __half        g_bm16[Hd * Hd];   // main B: fp16(Wy rows) [g][k]
__device__ __nv_bfloat16 g_bm8 [Hd * Hd];   // bf16 residual

// ---------------- helpers ----------------
__device__ __forceinline__ uint32_t smem_u32(const void* p) {
    uint32_t a;
    asm("{ .reg .u64 t; cvta.to.shared.u64 t, %1; cvt.u32.u64 %0, t; }" : "=r"(a) : "l"(p));
    return a;
}
__device__ __forceinline__ void cp16(uint32_t saddr, const void* gptr) {
    asm volatile("cp.async.cg.shared.global [%0], [%1], 16;" :: "r"(saddr), "l"(gptr));
}
__device__ __forceinline__ void ldsm4(uint32_t* r, uint32_t addr) {
    asm volatile("ldmatrix.sync.aligned.m8n8.x4.shared.b16 {%0,%1,%2,%3}, [%4];"
                 : "=r"(r[0]), "=r"(r[1]), "=r"(r[2]), "=r"(r[3]) : "r"(addr));
}
__device__ __forceinline__ void mma_bf(float* c, const uint32_t* a, const uint32_t* b) {
    asm volatile(
        "mma.sync.aligned.m16n8k16.row.col.f32.bf16.bf16.f32 "
        "{%0,%1,%2,%3}, {%4,%5,%6,%7}, {%8,%9}, {%0,%1,%2,%3};"
        : "+f"(c[0]), "+f"(c[1]), "+f"(c[2]), "+f"(c[3])
        : "r"(a[0]), "r"(a[1]), "r"(a[2]), "r"(a[3]), "r"(b[0]), "r"(b[1]));
}
__device__ __forceinline__ void mma_h(float* c, const uint32_t* a, const uint32_t* b) {
    asm volatile(
        "mma.sync.aligned.m16n8k16.row.col.f32.f16.f16.f32 "
        "{%0,%1,%2,%3}, {%4,%5,%6,%7}, {%8,%9}, {%0,%1,%2,%3};"
        : "+f"(c[0]), "+f"(c[1]), "+f"(c[2]), "+f"(c[3])
        : "r"(a[0]), "r"(a[1]), "r"(a[2]), "r"(a[3]), "r"(b[0]), "r"(b[1]));
}
__device__ __forceinline__ float fsig(float x)  { return __fdividef(1.f, 1.f + __expf(-x)); }
__device__ __forceinline__ float ftanh(float x) { return 1.f - __fdividef(2.f, __expf(2.f * x) + 1.f); }

// fp32x2 (k_ci)
__device__ __forceinline__ void ffma2(unsigned long long& c, unsigned long long a, unsigned long long b) {
    asm("fma.rn.f32x2 %0, %1, %2, %0;" : "+l"(c) : "l"(a), "l"(b));
}
__device__ __forceinline__ float2 unpack2(unsigned long long v) {
    unsigned int lo, hi;
    asm("mov.b64 {%0, %1}, %2;" : "=r"(lo), "=r"(hi) : "l"(v));
    return make_float2(__uint_as_float(lo), __uint_as_float(hi));
}

// pack helpers
__device__ __forceinline__ unsigned pkb(float a, float b) {
    __nv_bfloat162 t = __floats2bfloat162_rn(a, b);
    return *reinterpret_cast<unsigned*>(&t);
}
__device__ __forceinline__ unsigned pkh(float a, float b) {
    __half2 t = __floats2half2_rn(a, b);
    return *reinterpret_cast<unsigned*>(&t);
}
__device__ __forceinline__ float rh(float a) { return __half2float(__float2half_rn(a)); }

// swizzled offset inside a [rows x 64 b16] tile (128 B rows)
__device__ __forceinline__ uint32_t sw(int row, int c8) {
    return (uint32_t)(row * 128 + ((c8 ^ (row & 7)) << 4));
}

// ============================================================================
// Conversion kernels: activations -> fp16 + bf16(full); weights -> fp16 hi + bf16 lo
// ============================================================================
__global__ __launch_bounds__(128) void k_cvt_x(const float* __restrict__ x) {
    const int r = blockIdx.x;
    const int t = threadIdx.x;
    float4 v = *(const float4*)(x + ((size_t)r << 9) + t * 4);
    uint2 h, l;
    h.x = pkh(v.x, v.y); h.y = pkh(v.z, v.w);
    l.x = pkb(v.x, v.y); l.y = pkb(v.z, v.w);
    ((uint2*)g_x16)[(size_t)r * 128 + t] = h;
    ((uint2*)g_x8)[(size_t)r * 128 + t] = l;
}

__global__ __launch_bounds__(128) void k_cvt_y(const float* __restrict__ y) {
    const int r = blockIdx.x;                // compact row in [0, 65024)
    const int t = threadIdx.x;
    const int b = r / (127 * Nn);
    const int rem = r - b * (127 * Nn);
    const int sp = rem >> 6, n = rem & 63;
    const float* src = y + ((((size_t)(b * Sn) + sp + 1) * Nn + n) << 9) + t * 4;
    float4 v = *(const float4*)src;
    uint2 h, l;
    h.x = pkh(v.x, v.y); h.y = pkh(v.z, v.w);
    l.x = pkb(v.x, v.y); l.y = pkb(v.z, v.w);
    ((uint2*)g_y16)[(size_t)r * 128 + t] = h;
    ((uint2*)g_y8)[(size_t)r * 128 + t] = l;
}

__global__ __launch_bounds__(128) void k_cvt_w(const float* __restrict__ Wa1,
                                               const float* __restrict__ Wl) {
    const int g = blockIdx.x;
    const int t = threadIdx.x;
    {   // main B: Wl row g, first Hd cols (Wy)
        float4 v = *(const float4*)(Wl + (size_t)g * 1024 + t * 4);
        uint2 h, l;
        h.x = pkh(v.x, v.y); h.y = pkh(v.z, v.w);
        l.x = pkb(v.x - rh(v.x), v.y - rh(v.y));
        l.y = pkb(v.z - rh(v.z), v.w - rh(v.w));
        ((uint2*)g_bm16)[(size_t)g * 128 + t] = h;
        ((uint2*)g_bm8)[(size_t)g * 128 + t] = l;
    }
    {   // scores B: Wa1^T row g
        int k0 = t * 4;
        float a = Wa1[(size_t)(k0 + 0) * Hd + g];
        float b = Wa1[(size_t)(k0 + 1) * Hd + g];
        float c = Wa1[(size_t)(k0 + 2) * Hd + g];
        float d = Wa1[(size_t)(k0 + 3) * Hd + g];
        uint2 h, l;
        h.x = pkh(a, b); h.y = pkh(c, d);
        l.x = pkb(a - rh(a), b - rh(b));
        l.y = pkb(c - rh(c), d - rh(d));
        ((uint2*)g_bs16)[(size_t)g * 128 + t] = h;
        ((uint2*)g_bs8)[(size_t)g * 128 + t] = l;
    }
}

// ============================================================================
// Pipelined hybrid mainloop: block tile 256(M) x 128(N), K=512 in 64-chunks.
// Stage: A16 32K | A8 32K | B16 16K | B8 16K = 96 KB. 2 stages (192 KB).
// 512 threads, warp grid 4(M) x 4(N), warp tile 64x32.
// 2 terms: A_fp16*Bhi_fp16 + A_bf16*Blo_bf16, fp32 accumulate.
// ============================================================================
#define STG   98304
#define DSMEM (2 * STG + 128)

__device__ __forceinline__ void hmma_loop2(
    const __half* __restrict__ A16, const __nv_bfloat16* __restrict__ A8,
    const __half* __restrict__ B16, const __nv_bfloat16* __restrict__ B8,
    uint32_t smu, float acc[4][4][4])
{
    const int tid = threadIdx.x;
    const int lid = tid & 31, wid = tid >> 5;
    const int wm = wid >> 2, wn = wid & 3;

    int rowA[4], c8A[4], rowB[2], c8B[2];
    uint32_t soA[4], soB[2];
#pragma unroll
    for (int i = 0; i < 4; i++) {
        int id = tid + 512 * i;
        rowA[i] = id >> 3; c8A[i] = id & 7;
        soA[i] = sw(rowA[i], c8A[i]);
    }
#pragma unroll
    for (int i = 0; i < 2; i++) {
        int id = tid + 512 * i;
        rowB[i] = id >> 3; c8B[i] = id & 7;
        soB[i] = sw(rowB[i], c8B[i]);
    }

    const int rowA_base = wm * 64 + (lid & 15);
    const int c8A_half = lid >> 4;
    const int rowB_base = wn * 32 + ((lid >> 4) << 3) + (lid & 7);
    const int c8B_half = (lid >> 3) & 1;

    // prefetch chunk 0
    {
        const uint32_t b0 = smu;
#pragma unroll
        for (int i = 0; i < 4; i++) {
            const size_t go = (size_t)rowA[i] * Hd + c8A[i] * 8;
            cp16(b0 + soA[i], A16 + go);
            cp16(b0 + 32768 + soA[i], A8 + go);
        }
#pragma unroll
        for (int i = 0; i < 2; i++) {
            const size_t go = (size_t)rowB[i] * Hd + c8B[i] * 8;
            cp16(b0 + 65536 + soB[i], B16 + go);
            cp16(b0 + 81920 + soB[i], B8 + go);
        }
        asm volatile("cp.async.commit_group;");
    }

    for (int it = 0; it < 8; ++it) {
        const int s = it & 1;
        if (it < 7) {       // prefetch next chunk into other stage
            const uint32_t b1 = smu + (s ^ 1) * STG;
            const int kk = (it + 1) * 64;
#pragma unroll
            for (int i = 0; i < 4; i++) {
                const size_t go = (size_t)rowA[i] * Hd + kk + c8A[i] * 8;
                cp16(b1 + soA[i], A16 + go);
                cp16(b1 + 32768 + soA[i], A8 + go);
            }
#pragma unroll
            for (int i = 0; i < 2; i++) {
                const size_t go = (size_t)rowB[i] * Hd + kk + c8B[i] * 8;
                cp16(b1 + 65536 + soB[i], B16 + go);
                cp16(b1 + 81920 + soB[i], B8 + go);
            }
            asm volatile("cp.async.commit_group;");
            asm volatile("cp.async.wait_group 1;" ::: "memory");
        } else {
            asm volatile("cp.async.wait_group 0;" ::: "memory");
        }
        __syncthreads();

        const uint32_t b0 = smu + s * STG;
#pragma unroll
        for (int ks = 0; ks < 4; ks++) {
            uint32_t bh[8], bl[8];
#pragma unroll
            for (int q = 0; q < 2; q++) {
                uint32_t off = sw(rowB_base + q * 16, ks * 2 + c8B_half);
                ldsm4(&bh[q * 4], b0 + 65536 + off);
                ldsm4(&bl[q * 4], b0 + 81920 + off);
            }
#pragma unroll
            for (int mf = 0; mf < 4; mf++) {
                uint32_t off = sw(rowA_base + mf * 16, ks * 2 + c8A_half);
                uint32_t a16[4], a8[4];
                ldsm4(a16, b0 + off);
                ldsm4(a8, b0 + 32768 + off);
#pragma unroll
                for (int nf = 0; nf < 4; nf++) {
                    mma_h(acc[mf][nf], a16, &bh[nf * 2]);
                    mma_bf(acc[mf][nf], a8, &bl[nf * 2]);
                }
            }
        }
        __syncthreads();
    }
}

// ============================================================================
// k_scores_mma: pre = x@Wa1 (+ba1); partial scores = sum_g tanh(pre)*wa2
// grid (128, 4), 512 threads
// ============================================================================
__global__ __launch_bounds__(512, 1) void k_scores_mma(
    const float* __restrict__ ba1, const float* __restrict__ wa2)
{
    extern __shared__ char dyn[];
    const uint32_t smu = (smem_u32(dyn) + 127) & ~127u;

    const int row0 = blockIdx.x * 256;
    const int gg = blockIdx.y * 128;
    const int tid = threadIdx.x;
    const int lid = tid & 31, wid = tid >> 5;
    const int wm = wid >> 2, wn = wid & 3;
    const int groupID = lid >> 2, tig = lid & 3;

    float acc[4][4][4];
#pragma unroll
    for (int a = 0; a < 4; a++)
#pragma unroll
        for (int b = 0; b < 4; b++)
#pragma unroll
            for (int c = 0; c < 4; c++) acc[a][b][c] = 0.f;

    hmma_loop2(g_x16 + ((size_t)row0 << 9), g_x8 + ((size_t)row0 << 9),
               g_bs16 + ((size_t)gg << 9),  g_bs8 + ((size_t)gg << 9),
               smu, acc);

    const int colw = gg + wn * 32;
#pragma unroll
    for (int mf = 0; mf < 4; mf++) {
#pragma unroll
        for (int half = 0; half < 2; half++) {
            const int R = row0 + wm * 64 + mf * 16 + groupID + half * 8;
            float s = 0.f;
#pragma unroll
            for (int nf = 0; nf < 4; nf++) {
                const int g = colw + nf * 8 + tig * 2;
                float a0 = acc[mf][nf][half * 2 + 0];
                float a1 = acc[mf][nf][half * 2 + 1];
                s += ftanh(a0 + __ldg(ba1 + g))     * __ldg(wa2 + g);
                s += ftanh(a1 + __ldg(ba1 + g + 1)) * __ldg(wa2 + g + 1);
            }
            s += __shfl_xor_sync(0xffffffffu, s, 1);
            s += __shfl_xor_sync(0xffffffffu, s, 2);
            if (tig == 0)
                g_spart[(blockIdx.y * 4 + wn) * ROWS_X + R] = s;
        }
    }
}

// ============================================================================
// k_main_mma: pre = y@Wy^T + ci ; out = y + i_x*sigmoid(pre)
// grid (254, 4), 512 threads
// ============================================================================
__global__ __launch_bounds__(512, 1) void k_main_mma(
    const float* __restrict__ y, float* __restrict__ out)
{
    extern __shared__ char dyn[];
    const uint32_t smu = (smem_u32(dyn) + 127) & ~127u;

    const int row0 = blockIdx.x * 256;
    const int gg = blockIdx.y * 128;
    const int tid = threadIdx.x;
    const int lid = tid & 31, wid = tid >> 5;
    const int wm = wid >> 2, wn = wid & 3;
    const int groupID = lid >> 2, tig = lid & 3;

    float acc[4][4][4];
#pragma unroll
    for (int a = 0; a < 4; a++)
#pragma unroll
        for (int b = 0; b < 4; b++)
#pragma unroll
            for (int c = 0; c < 4; c++) acc[a][b][c] = 0.f;

    hmma_loop2(g_y16 + ((size_t)row0 << 9), g_y8 + ((size_t)row0 << 9),
               g_bm16 + ((size_t)gg << 9),  g_bm8 + ((size_t)gg << 9),
               smu, acc);

    const int colw = gg + wn * 32;
#pragma unroll
    for (int mf = 0; mf < 4; mf++) {
#pragma unroll
        for (int half = 0; half < 2; half++) {
            const int R = row0 + wm * 64 + mf * 16 + groupID + half * 8;
            const int b = R / 8128;
            const int rem = R - b * 8128;
            const int sp = rem >> 6, n = rem & 63;
            const size_t ybase = ((((size_t)(b * Sn) + sp + 1) * Nn + n) << 9) + colw;
            const float* cib = g_ci + (((size_t)(b * 127 + sp)) << 9) + colw;
            const float* ixb = g_pooled + (((size_t)(b * Sn) + sp) << 9) + colw;
#pragma unroll
            for (int nf = 0; nf < 4; nf++) {
                const int c = nf * 8 + tig * 2;
                float a0 = acc[mf][nf][half * 2 + 0];
                float a1 = acc[mf][nf][half * 2 + 1];
                float2 ci2 = *(const float2*)(cib + c);
                float2 ix2 = *(const float2*)(ixb + c);
                float2 y2  = *(const float2*)(y + ybase + c);
                float2 o;
                o.x = y2.x + ix2.x * fsig(a0 + ci2.x);
                o.y = y2.y + ix2.y * fsig(a1 + ci2.y);
                *(float2*)(out + ybase + c) = o;
            }
        }
    }
}

// ============================================================================
// k_pool: softmax over m + weighted pool (sums 16 score partials)
// ============================================================================
__global__ __launch_bounds__(256) void k_pool(const float* __restrict__ x)
{
    const int bs = blockIdx.x;
    __shared__ float attn[32];
    const int tid = threadIdx.x;
    if (tid < 32) {
        float s = 0.f;
#pragma unroll
        for (int q = 0; q < NSLICE; q++) s += g_spart[q * ROWS_X + bs * Mn + tid];
        float mx = s;
#pragma unroll
        for (int o = 16; o > 0; o >>= 1)
            mx = fmaxf(mx, __shfl_xor_sync(0xffffffffu, mx, o));
        float e = expf(s - mx);
        float sum = e;
#pragma unroll
        for (int o = 16; o > 0; o >>= 1)
            sum += __shfl_xor_sync(0xffffffffu, sum, o);
        attn[tid] = e / sum;
    }
    __syncthreads();
    const float* xb = x + (size_t)bs * Mn * Hd;
    for (int h = tid; h < Hd; h += 256) {
        float s = 0.f;
#pragma unroll
        for (int m = 0; m < Mn; m++) s = fmaf(attn[m], xb[(size_t)m * Hd + h], s);
        g_pooled[(size_t)bs * Hd + h] = s;
    }
}

// ============================================================================
// k_ci (FFMA2): ci = pooled @ Wi^T + bl
// ============================================================================
__global__ __launch_bounds__(256) void k_ci(
    const float* __restrict__ Wl, const float* __restrict__ bl)
{
    const int b = blockIdx.x >> 2;
    const int s0 = (blockIdx.x & 3) * 32;
    const int tid = threadIdx.x;
    const int tg = tid & 63;
    const int tm = tid >> 6;

    __shared__ __align__(16) float2 As2[16][32];
    __shared__ __align__(16) float  Bs[16][516];

    unsigned long long acc[8][4];
#pragma unroll
    for (int i = 0; i < 8; i++)
#pragma unroll
        for (int j = 0; j < 4; j++) acc[i][j] = 0ull;

    for (int kk = 0; kk < Hd; kk += 16) {
        if (tid < 128) {
            int m = tid >> 2, k4 = (tid & 3) * 4;
            int sp = s0 + m;
            float4 v = make_float4(0.f, 0.f, 0.f, 0.f);
            if (sp < 127)
                v = *(const float4*)(g_pooled + ((size_t)b * Sn + sp) * Hd + kk + k4);
            As2[k4 + 0][m] = make_float2(v.x, v.x);
            As2[k4 + 1][m] = make_float2(v.y, v.y);
            As2[k4 + 2][m] = make_float2(v.z, v.z);
            As2[k4 + 3][m] = make_float2(v.w, v.w);
        }
#pragma unroll
        for (int q = 0; q < 8; q++) {
            int f = tid + 256 * q;
            int g = f >> 2, k4 = (f & 3) * 4;
            float4 v = *(const float4*)(Wl + (size_t)g * (2 * Hd) + Hd + kk + k4);
            Bs[k4 + 0][g] = v.x;
            Bs[k4 + 1][g] = v.y;
            Bs[k4 + 2][g] = v.z;
            Bs[k4 + 3][g] = v.w;
        }
        __syncthreads();
#pragma unroll
        for (int k = 0; k < 16; k++) {
            unsigned long long a2[8], b2[4];
#pragma unroll
            for (int i = 0; i < 8; i++)
                a2[i] = *(const unsigned long long*)&As2[k][tm + 4 * i];
#pragma unroll
            for (int j = 0; j < 4; j++)
                b2[j] = *(const unsigned long long*)&Bs[k][2 * tg + 128 * j];
#pragma unroll
            for (int i = 0; i < 8; i++)
#pragma unroll
                for (int j = 0; j < 4; j++) ffma2(acc[i][j], a2[i], b2[j]);
        }
        __syncthreads();
    }

#pragma unroll
    for (int i = 0; i < 8; i++) {
        int sp = s0 + tm + 4 * i;
        if (sp < 127) {
            float* crow = g_ci + ((size_t)b * 127 + sp) * Hd;
#pragma unroll
            for (int j = 0; j < 4; j++) {
                int g = 2 * tg + 128 * j;
                float2 p = unpack2(acc[i][j]);
                crow[g]     = p.x + bl[g];
                crow[g + 1] = p.y + bl[g + 1];
            }
        }
    }
}

// ============================================================================
// k_copy0: out[:, 0] = y[:, 0]
// ============================================================================
__global__ __launch_bounds__(256) void k_copy0(
    const float* __restrict__ y, float* __restrict__ out)
{
    const int b = blockIdx.y;
    const int i = (blockIdx.x * 256 + threadIdx.x) * 4;
    const size_t base = (size_t)b * Sn * Nn * Hd;
    if (i < Nn * Hd)
        *(float4*)(out + base + i) = *(const float4*)(y + base + i);
}

extern "C" void kernel_launch(void* const* d_in, const int* in_sizes, int n_in,
                              void* d_out, int out_size)
{
    const float* x   = (const float*)d_in[0];
    const float* y   = (const float*)d_in[1];
    const float* Wa1 = (const float*)d_in[2];
    const float* ba1 = (const float*)d_in[3];
    const float* wa2 = (const float*)d_in[4];
    const float* Wl  = (const float*)d_in[5];
    const float* bl  = (const float*)d_in[6];
    float* out = (float*)d_out;

    cudaFuncSetAttribute(k_scores_mma, cudaFuncAttributeMaxDynamicSharedMemorySize, DSMEM);
    cudaFuncSetAttribute(k_main_mma,   cudaFuncAttributeMaxDynamicSharedMemorySize, DSMEM);

    k_cvt_w<<<Hd, 128>>>(Wa1, Wl);
    k_cvt_x<<<ROWS_X, 128>>>(x);
    k_cvt_y<<<ROWS_Y, 128>>>(y);
    k_scores_mma<<<dim3(ROWS_X / 256, 4), 512, DSMEM>>>(ba1, wa2);
    k_pool<<<Bn * Sn, 256>>>(x);
    k_ci<<<Bn * 4, 256>>>(Wl, bl);
    k_main_mma<<<dim3(ROWS_Y / 256, 4), 512, DSMEM>>>(y, out);
    k_copy0<<<dim3((Nn * Hd / 4 + 255) / 256, Bn), 256>>>(y, out);
}

// round 6
// speedup vs baseline: 4.0545x; 1.4222x over previous
#include <cuda_runtime.h>
#include <cuda_fp16.h>
#include <cstdint>

#define Hd 512
#define Bn 8
#define Sn 128
#define Mn 32
#define Nn 64

#define ROWS_Y  (Bn * (Sn - 1) * Nn)   // 65024 = 508*128
#define ROWS_X  (Bn * Sn * Mn)         // 32768 = 256*128
#define NSLICE  16

// ---------------- device scratch ----------------
__device__ float g_spart[NSLICE * ROWS_X];
__device__ float g_pooled[Bn * Sn * Hd];
__device__ float g_ci[Bn * (Sn - 1) * Hd];

__device__ __half g_x16[(size_t)ROWS_X * Hd];
__device__ __half g_y16[(size_t)ROWS_Y * Hd];
__device__ __half g_bs16[Hd * Hd];   // scores B: fp16(Wa1^T) [g][k]
__device__ __half g_bm16[Hd * Hd];   // main B: fp16(Wy rows) [g][k]

// ---------------- helpers ----------------
__device__ __forceinline__ uint32_t smem_u32(const void* p) {
    uint32_t a;
    asm("{ .reg .u64 t; cvta.to.shared.u64 t, %1; cvt.u32.u64 %0, t; }" : "=r"(a) : "l"(p));
    return a;
}
__device__ __forceinline__ void cp16(uint32_t saddr, const void* gptr) {
    asm volatile("cp.async.cg.shared.global [%0], [%1], 16;" :: "r"(saddr), "l"(gptr));
}
__device__ __forceinline__ void ldsm4(uint32_t* r, uint32_t addr) {
    asm volatile("ldmatrix.sync.aligned.m8n8.x4.shared.b16 {%0,%1,%2,%3}, [%4];"
                 : "=r"(r[0]), "=r"(r[1]), "=r"(r[2]), "=r"(r[3]) : "r"(addr));
}
__device__ __forceinline__ void mma_h(float* c, const uint32_t* a, const uint32_t* b) {
    asm volatile(
        "mma.sync.aligned.m16n8k16.row.col.f32.f16.f16.f32 "
        "{%0,%1,%2,%3}, {%4,%5,%6,%7}, {%8,%9}, {%0,%1,%2,%3};"
        : "+f"(c[0]), "+f"(c[1]), "+f"(c[2]), "+f"(c[3])
        : "r"(a[0]), "r"(a[1]), "r"(a[2]), "r"(a[3]), "r"(b[0]), "r"(b[1]));
}
__device__ __forceinline__ float fsig(float x)  { return __fdividef(1.f, 1.f + __expf(-x)); }
__device__ __forceinline__ float ftanh(float x) { return 1.f - __fdividef(2.f, __expf(2.f * x) + 1.f); }

// fp32x2 (k_ci)
__device__ __forceinline__ void ffma2(unsigned long long& c, unsigned long long a, unsigned long long b) {
    asm("fma.rn.f32x2 %0, %1, %2, %0;" : "+l"(c) : "l"(a), "l"(b));
}
__device__ __forceinline__ float2 unpack2(unsigned long long v) {
    unsigned int lo, hi;
    asm("mov.b64 {%0, %1}, %2;" : "=r"(lo), "=r"(hi) : "l"(v));
    return make_float2(__uint_as_float(lo), __uint_as_float(hi));
}

__device__ __forceinline__ unsigned pkh(float a, float b) {
    __half2 t = __floats2half2_rn(a, b);
    return *reinterpret_cast<unsigned*>(&t);
}

// swizzled offset inside a [rows x 64 fp16] tile (128 B rows)
__device__ __forceinline__ uint32_t sw(int row, int c8) {
    return (uint32_t)(row * 128 + ((c8 ^ (row & 7)) << 4));
}

// ============================================================================
// Conversion kernels (fp16 only)
// ============================================================================
__global__ __launch_bounds__(128) void k_cvt_x(const float* __restrict__ x) {
    const int r = blockIdx.x;
    const int t = threadIdx.x;
    float4 v = *(const float4*)(x + ((size_t)r << 9) + t * 4);
    uint2 h;
    h.x = pkh(v.x, v.y); h.y = pkh(v.z, v.w);
    ((uint2*)g_x16)[(size_t)r * 128 + t] = h;
}

__global__ __launch_bounds__(128) void k_cvt_y(const float* __restrict__ y) {
    const int r = blockIdx.x;                // compact row in [0, 65024)
    const int t = threadIdx.x;
    const int b = r / (127 * Nn);
    const int rem = r - b * (127 * Nn);
    const int sp = rem >> 6, n = rem & 63;
    const float* src = y + ((((size_t)(b * Sn) + sp + 1) * Nn + n) << 9) + t * 4;
    float4 v = *(const float4*)src;
    uint2 h;
    h.x = pkh(v.x, v.y); h.y = pkh(v.z, v.w);
    ((uint2*)g_y16)[(size_t)r * 128 + t] = h;
}

__global__ __launch_bounds__(128) void k_cvt_w(const float* __restrict__ Wa1,
                                               const float* __restrict__ Wl) {
    const int g = blockIdx.x;
    const int t = threadIdx.x;
    {   // main B: Wl row g, first Hd cols (Wy)
        float4 v = *(const float4*)(Wl + (size_t)g * 1024 + t * 4);
        uint2 h;
        h.x = pkh(v.x, v.y); h.y = pkh(v.z, v.w);
        ((uint2*)g_bm16)[(size_t)g * 128 + t] = h;
    }
    {   // scores B: Wa1^T row g
        int k0 = t * 4;
        float a = Wa1[(size_t)(k0 + 0) * Hd + g];
        float b = Wa1[(size_t)(k0 + 1) * Hd + g];
        float c = Wa1[(size_t)(k0 + 2) * Hd + g];
        float d = Wa1[(size_t)(k0 + 3) * Hd + g];
        uint2 h;
        h.x = pkh(a, b); h.y = pkh(c, d);
        ((uint2*)g_bs16)[(size_t)g * 128 + t] = h;
    }
}

// ============================================================================
// Pipelined single-term fp16 mainloop: block 128(M) x 128(N), K=512 in 64-chunks.
// Stage: A 16K | B 16K = 32 KB; 2 stages. 256 threads, warps 2(M) x 4(N),
// warp tile 64x32, fp32 accumulate. 2 CTAs/SM.
// ============================================================================
#define STG   32768
#define DSMEM (2 * STG + 128)

__device__ __forceinline__ void hmma_loop1(
    const __half* __restrict__ A16, const __half* __restrict__ B16,
    uint32_t smu, float acc[4][4][4])
{
    const int tid = threadIdx.x;
    const int lid = tid & 31, wid = tid >> 5;
    const int wm = wid >> 2, wn = wid & 3;

    int rowS[4], c8S[4];
    uint32_t soS[4];
#pragma unroll
    for (int i = 0; i < 4; i++) {
        int id = tid + 256 * i;
        rowS[i] = id >> 3; c8S[i] = id & 7;
        soS[i] = sw(rowS[i], c8S[i]);
    }

    const int rowA_base = wm * 64 + (lid & 15);
    const int c8A_half = lid >> 4;
    const int rowB_base = wn * 32 + ((lid >> 4) << 3) + (lid & 7);
    const int c8B_half = (lid >> 3) & 1;

    // prefetch chunk 0
    {
        const uint32_t b0 = smu;
#pragma unroll
        for (int i = 0; i < 4; i++) {
            const size_t go = (size_t)rowS[i] * Hd + c8S[i] * 8;
            cp16(b0 + soS[i], A16 + go);
            cp16(b0 + 16384 + soS[i], B16 + go);
        }
        asm volatile("cp.async.commit_group;");
    }

    for (int it = 0; it < 8; ++it) {
        const int s = it & 1;
        if (it < 7) {
            const uint32_t b1 = smu + (s ^ 1) * STG;
            const int kk = (it + 1) * 64;
#pragma unroll
            for (int i = 0; i < 4; i++) {
                const size_t go = (size_t)rowS[i] * Hd + kk + c8S[i] * 8;
                cp16(b1 + soS[i], A16 + go);
                cp16(b1 + 16384 + soS[i], B16 + go);
            }
            asm volatile("cp.async.commit_group;");
            asm volatile("cp.async.wait_group 1;" ::: "memory");
        } else {
            asm volatile("cp.async.wait_group 0;" ::: "memory");
        }
        __syncthreads();

        const uint32_t b0 = smu + s * STG;
#pragma unroll
        for (int ks = 0; ks < 4; ks++) {
            uint32_t bh[8];
#pragma unroll
            for (int q = 0; q < 2; q++) {
                uint32_t off = sw(rowB_base + q * 16, ks * 2 + c8B_half);
                ldsm4(&bh[q * 4], b0 + 16384 + off);
            }
#pragma unroll
            for (int mf = 0; mf < 4; mf++) {
                uint32_t off = sw(rowA_base + mf * 16, ks * 2 + c8A_half);
                uint32_t a16[4];
                ldsm4(a16, b0 + off);
#pragma unroll
                for (int nf = 0; nf < 4; nf++)
                    mma_h(acc[mf][nf], a16, &bh[nf * 2]);
            }
        }
        __syncthreads();
    }
}

// ============================================================================
// k_scores_mma: pre = x@Wa1 (+ba1); partial scores = sum_g tanh(pre)*wa2
// grid (256, 4), 256 threads
// ============================================================================
__global__ __launch_bounds__(256, 2) void k_scores_mma(
    const float* __restrict__ ba1, const float* __restrict__ wa2)
{
    extern __shared__ char dyn[];
    const uint32_t smu = (smem_u32(dyn) + 127) & ~127u;

    const int row0 = blockIdx.x * 128;
    const int gg = blockIdx.y * 128;
    const int tid = threadIdx.x;
    const int lid = tid & 31, wid = tid >> 5;
    const int wm = wid >> 2, wn = wid & 3;
    const int groupID = lid >> 2, tig = lid & 3;

    float acc[4][4][4];
#pragma unroll
    for (int a = 0; a < 4; a++)
#pragma unroll
        for (int b = 0; b < 4; b++)
#pragma unroll
            for (int c = 0; c < 4; c++) acc[a][b][c] = 0.f;

    hmma_loop1(g_x16 + ((size_t)row0 << 9), g_bs16 + ((size_t)gg << 9), smu, acc);

    const int colw = gg + wn * 32;
#pragma unroll
    for (int mf = 0; mf < 4; mf++) {
#pragma unroll
        for (int half = 0; half < 2; half++) {
            const int R = row0 + wm * 64 + mf * 16 + groupID + half * 8;
            float s = 0.f;
#pragma unroll
            for (int nf = 0; nf < 4; nf++) {
                const int g = colw + nf * 8 + tig * 2;
                float a0 = acc[mf][nf][half * 2 + 0];
                float a1 = acc[mf][nf][half * 2 + 1];
                s += ftanh(a0 + __ldg(ba1 + g))     * __ldg(wa2 + g);
                s += ftanh(a1 + __ldg(ba1 + g + 1)) * __ldg(wa2 + g + 1);
            }
            s += __shfl_xor_sync(0xffffffffu, s, 1);
            s += __shfl_xor_sync(0xffffffffu, s, 2);
            if (tig == 0)
                g_spart[(blockIdx.y * 4 + wn) * ROWS_X + R] = s;
        }
    }
}

// ============================================================================
// k_main_mma: pre = y@Wy^T + ci ; out = y + i_x*sigmoid(pre)
// grid (508, 4), 256 threads
// ============================================================================
__global__ __launch_bounds__(256, 2) void k_main_mma(
    const float* __restrict__ y, float* __restrict__ out)
{
    extern __shared__ char dyn[];
    const uint32_t smu = (smem_u32(dyn) + 127) & ~127u;

    const int row0 = blockIdx.x * 128;
    const int gg = blockIdx.y * 128;
    const int tid = threadIdx.x;
    const int lid = tid & 31, wid = tid >> 5;
    const int wm = wid >> 2, wn = wid & 3;
    const int groupID = lid >> 2, tig = lid & 3;

    float acc[4][4][4];
#pragma unroll
    for (int a = 0; a < 4; a++)
#pragma unroll
        for (int b = 0; b < 4; b++)
#pragma unroll
            for (int c = 0; c < 4; c++) acc[a][b][c] = 0.f;

    hmma_loop1(g_y16 + ((size_t)row0 << 9), g_bm16 + ((size_t)gg << 9), smu, acc);

    const int colw = gg + wn * 32;
#pragma unroll
    for (int mf = 0; mf < 4; mf++) {
#pragma unroll
        for (int half = 0; half < 2; half++) {
            const int R = row0 + wm * 64 + mf * 16 + groupID + half * 8;
            const int b = R / 8128;
            const int rem = R - b * 8128;
            const int sp = rem >> 6, n = rem & 63;
            const size_t ybase = ((((size_t)(b * Sn) + sp + 1) * Nn + n) << 9) + colw;
            const float* cib = g_ci + (((size_t)(b * 127 + sp)) << 9) + colw;
            const float* ixb = g_pooled + (((size_t)(b * Sn) + sp) << 9) + colw;
#pragma unroll
            for (int nf = 0; nf < 4; nf++) {
                const int c = nf * 8 + tig * 2;
                float a0 = acc[mf][nf][half * 2 + 0];
                float a1 = acc[mf][nf][half * 2 + 1];
                float2 ci2 = *(const float2*)(cib + c);
                float2 ix2 = *(const float2*)(ixb + c);
                float2 y2  = *(const float2*)(y + ybase + c);
                float2 o;
                o.x = y2.x + ix2.x * fsig(a0 + ci2.x);
                o.y = y2.y + ix2.y * fsig(a1 + ci2.y);
                *(float2*)(out + ybase + c) = o;
            }
        }
    }
}

// ============================================================================
// k_pool: softmax over m + weighted pool (sums 16 score partials)
// ============================================================================
__global__ __launch_bounds__(256) void k_pool(const float* __restrict__ x)
{
    const int bs = blockIdx.x;
    __shared__ float attn[32];
    const int tid = threadIdx.x;
    if (tid < 32) {
        float s = 0.f;
#pragma unroll
        for (int q = 0; q < NSLICE; q++) s += g_spart[q * ROWS_X + bs * Mn + tid];
        float mx = s;
#pragma unroll
        for (int o = 16; o > 0; o >>= 1)
            mx = fmaxf(mx, __shfl_xor_sync(0xffffffffu, mx, o));
        float e = expf(s - mx);
        float sum = e;
#pragma unroll
        for (int o = 16; o > 0; o >>= 1)
            sum += __shfl_xor_sync(0xffffffffu, sum, o);
        attn[tid] = e / sum;
    }
    __syncthreads();
    const float* xb = x + (size_t)bs * Mn * Hd;
    for (int h = tid; h < Hd; h += 256) {
        float s = 0.f;
#pragma unroll
        for (int m = 0; m < Mn; m++) s = fmaf(attn[m], xb[(size_t)m * Hd + h], s);
        g_pooled[(size_t)bs * Hd + h] = s;
    }
}

// ============================================================================
// k_ci (FFMA2): ci = pooled @ Wi^T + bl
// ============================================================================
__global__ __launch_bounds__(256) void k_ci(
    const float* __restrict__ Wl, const float* __restrict__ bl)
{
    const int b = blockIdx.x >> 2;
    const int s0 = (blockIdx.x & 3) * 32;
    const int tid = threadIdx.x;
    const int tg = tid & 63;
    const int tm = tid >> 6;

    __shared__ __align__(16) float2 As2[16][32];
    __shared__ __align__(16) float  Bs[16][516];

    unsigned long long acc[8][4];
#pragma unroll
    for (int i = 0; i < 8; i++)
#pragma unroll
        for (int j = 0; j < 4; j++) acc[i][j] = 0ull;

    for (int kk = 0; kk < Hd; kk += 16) {
        if (tid < 128) {
            int m = tid >> 2, k4 = (tid & 3) * 4;
            int sp = s0 + m;
            float4 v = make_float4(0.f, 0.f, 0.f, 0.f);
            if (sp < 127)
                v = *(const float4*)(g_pooled + ((size_t)b * Sn + sp) * Hd + kk + k4);
            As2[k4 + 0][m] = make_float2(v.x, v.x);
            As2[k4 + 1][m] = make_float2(v.y, v.y);
            As2[k4 + 2][m] = make_float2(v.z, v.z);
            As2[k4 + 3][m] = make_float2(v.w, v.w);
        }
#pragma unroll
        for (int q = 0; q < 8; q++) {
            int f = tid + 256 * q;
            int g = f >> 2, k4 = (f & 3) * 4;
            float4 v = *(const float4*)(Wl + (size_t)g * (2 * Hd) + Hd + kk + k4);
            Bs[k4 + 0][g] = v.x;
            Bs[k4 + 1][g] = v.y;
            Bs[k4 + 2][g] = v.z;
            Bs[k4 + 3][g] = v.w;
        }
        __syncthreads();
#pragma unroll
        for (int k = 0; k < 16; k++) {
            unsigned long long a2[8], b2[4];
#pragma unroll
            for (int i = 0; i < 8; i++)
                a2[i] = *(const unsigned long long*)&As2[k][tm + 4 * i];
#pragma unroll
            for (int j = 0; j < 4; j++)
                b2[j] = *(const unsigned long long*)&Bs[k][2 * tg + 128 * j];
#pragma unroll
            for (int i = 0; i < 8; i++)
#pragma unroll
                for (int j = 0; j < 4; j++) ffma2(acc[i][j], a2[i], b2[j]);
        }
        __syncthreads();
    }

#pragma unroll
    for (int i = 0; i < 8; i++) {
        int sp = s0 + tm + 4 * i;
        if (sp < 127) {
            float* crow = g_ci + ((size_t)b * 127 + sp) * Hd;
#pragma unroll
            for (int j = 0; j < 4; j++) {
                int g = 2 * tg + 128 * j;
                float2 p = unpack2(acc[i][j]);
                crow[g]     = p.x + bl[g];
                crow[g + 1] = p.y + bl[g + 1];
            }
        }
    }
}

// ============================================================================
// k_copy0: out[:, 0] = y[:, 0]
// ============================================================================
__global__ __launch_bounds__(256) void k_copy0(
    const float* __restrict__ y, float* __restrict__ out)
{
    const int b = blockIdx.y;
    const int i = (blockIdx.x * 256 + threadIdx.x) * 4;
    const size_t base = (size_t)b * Sn * Nn * Hd;
    if (i < Nn * Hd)
        *(float4*)(out + base + i) = *(const float4*)(y + base + i);
}

extern "C" void kernel_launch(void* const* d_in, const int* in_sizes, int n_in,
                              void* d_out, int out_size)
{
    const float* x   = (const float*)d_in[0];
    const float* y   = (const float*)d_in[1];
    const float* Wa1 = (const float*)d_in[2];
    const float* ba1 = (const float*)d_in[3];
    const float* wa2 = (const float*)d_in[4];
    const float* Wl  = (const float*)d_in[5];
    const float* bl  = (const float*)d_in[6];
    float* out = (float*)d_out;

    cudaFuncSetAttribute(k_scores_mma, cudaFuncAttributeMaxDynamicSharedMemorySize, DSMEM);
    cudaFuncSetAttribute(k_main_mma,   cudaFuncAttributeMaxDynamicSharedMemorySize, DSMEM);

    k_cvt_w<<<Hd, 128>>>(Wa1, Wl);
    k_cvt_x<<<ROWS_X, 128>>>(x);
    k_cvt_y<<<ROWS_Y, 128>>>(y);
    k_scores_mma<<<dim3(ROWS_X / 128, 4), 256, DSMEM>>>(ba1, wa2);
    k_pool<<<Bn * Sn, 256>>>(x);
    k_ci<<<Bn * 4, 256>>>(Wl, bl);
    k_main_mma<<<dim3(ROWS_Y / 128, 4), 256, DSMEM>>>(y, out);
    k_copy0<<<dim3((Nn * Hd / 4 + 255) / 256, Bn), 256>>>(y, out);
}

// round 7
// speedup vs baseline: 5.2415x; 1.2928x over previous
#include <cuda_runtime.h>
#include <cuda_fp16.h>
#include <cstdint>

#define Hd 512
#define Bn 8
#define Sn 128
#define Mn 32
#define Nn 64

#define ROWS_Y  (Bn * (Sn - 1) * Nn)   // 65024 = 508*128
#define ROWS_X  (Bn * Sn * Mn)         // 32768 = 256*128
#define NSLICE  16

// ---------------- device scratch ----------------
__device__ float g_spart[NSLICE * ROWS_X];
__device__ float g_pooled[Bn * Sn * Hd];
__device__ float g_ci[Bn * (Sn - 1) * Hd];

__device__ __half g_x16[(size_t)ROWS_X * Hd];
__device__ __half g_y16[(size_t)ROWS_Y * Hd];
__device__ __half g_p16[(size_t)(Bn * Sn) * Hd];   // pooled fp16, row = b*128+s
__device__ __half g_bs16[Hd * Hd];   // scores B: fp16(Wa1^T) [g][k]
__device__ __half g_bm16[Hd * Hd];   // main B: fp16(Wy rows) [g][k]
__device__ __half g_bi16[Hd * Hd];   // ci B: fp16(Wi rows) [g][k]

// ---------------- helpers ----------------
__device__ __forceinline__ uint32_t smem_u32(const void* p) {
    uint32_t a;
    asm("{ .reg .u64 t; cvta.to.shared.u64 t, %1; cvt.u32.u64 %0, t; }" : "=r"(a) : "l"(p));
    return a;
}
__device__ __forceinline__ void cp16(uint32_t saddr, const void* gptr) {
    asm volatile("cp.async.cg.shared.global [%0], [%1], 16;" :: "r"(saddr), "l"(gptr));
}
__device__ __forceinline__ void ldsm4(uint32_t* r, uint32_t addr) {
    asm volatile("ldmatrix.sync.aligned.m8n8.x4.shared.b16 {%0,%1,%2,%3}, [%4];"
                 : "=r"(r[0]), "=r"(r[1]), "=r"(r[2]), "=r"(r[3]) : "r"(addr));
}
__device__ __forceinline__ void mma_h(float* c, const uint32_t* a, const uint32_t* b) {
    asm volatile(
        "mma.sync.aligned.m16n8k16.row.col.f32.f16.f16.f32 "
        "{%0,%1,%2,%3}, {%4,%5,%6,%7}, {%8,%9}, {%0,%1,%2,%3};"
        : "+f"(c[0]), "+f"(c[1]), "+f"(c[2]), "+f"(c[3])
        : "r"(a[0]), "r"(a[1]), "r"(a[2]), "r"(a[3]), "r"(b[0]), "r"(b[1]));
}
__device__ __forceinline__ float tanh_fast(float x) {
    float r;
    asm("tanh.approx.f32 %0, %1;" : "=f"(r) : "f"(x));
    return r;
}
// gate = sigmoid(x) = 0.5 + 0.5*tanh(0.5x)  (1 MUFU)
__device__ __forceinline__ float fsig(float x) {
    return fmaf(tanh_fast(0.5f * x), 0.5f, 0.5f);
}
// accurate-ish tanh for scores path (2 MUFU)
__device__ __forceinline__ float ftanh(float x) { return 1.f - __fdividef(2.f, __expf(2.f * x) + 1.f); }

__device__ __forceinline__ unsigned pkh(float a, float b) {
    __half2 t = __floats2half2_rn(a, b);
    return *reinterpret_cast<unsigned*>(&t);
}

// swizzled offset inside a [rows x 64 fp16] tile (128 B rows)
__device__ __forceinline__ uint32_t sw(int row, int c8) {
    return (uint32_t)(row * 128 + ((c8 ^ (row & 7)) << 4));
}

// ============================================================================
// Conversion kernels (fp16 only)
// ============================================================================
__global__ __launch_bounds__(128) void k_cvt_x(const float* __restrict__ x) {
    const int r = blockIdx.x;
    const int t = threadIdx.x;
    float4 v = *(const float4*)(x + ((size_t)r << 9) + t * 4);
    uint2 h;
    h.x = pkh(v.x, v.y); h.y = pkh(v.z, v.w);
    ((uint2*)g_x16)[(size_t)r * 128 + t] = h;
}

__global__ __launch_bounds__(128) void k_cvt_y(const float* __restrict__ y) {
    const int r = blockIdx.x;                // compact row in [0, 65024)
    const int t = threadIdx.x;
    const int b = r / (127 * Nn);
    const int rem = r - b * (127 * Nn);
    const int sp = rem >> 6, n = rem & 63;
    const float* src = y + ((((size_t)(b * Sn) + sp + 1) * Nn + n) << 9) + t * 4;
    float4 v = *(const float4*)src;
    uint2 h;
    h.x = pkh(v.x, v.y); h.y = pkh(v.z, v.w);
    ((uint2*)g_y16)[(size_t)r * 128 + t] = h;
}

__global__ __launch_bounds__(128) void k_cvt_w(const float* __restrict__ Wa1,
                                               const float* __restrict__ Wl) {
    const int g = blockIdx.x;
    const int t = threadIdx.x;
    {   // main B: Wl row g, first Hd cols (Wy)
        float4 v = *(const float4*)(Wl + (size_t)g * 1024 + t * 4);
        uint2 h;
        h.x = pkh(v.x, v.y); h.y = pkh(v.z, v.w);
        ((uint2*)g_bm16)[(size_t)g * 128 + t] = h;
    }
    {   // ci B: Wl row g, cols [Hd, 2Hd) (Wi)
        float4 v = *(const float4*)(Wl + (size_t)g * 1024 + Hd + t * 4);
        uint2 h;
        h.x = pkh(v.x, v.y); h.y = pkh(v.z, v.w);
        ((uint2*)g_bi16)[(size_t)g * 128 + t] = h;
    }
    {   // scores B: Wa1^T row g
        int k0 = t * 4;
        float a = Wa1[(size_t)(k0 + 0) * Hd + g];
        float b = Wa1[(size_t)(k0 + 1) * Hd + g];
        float c = Wa1[(size_t)(k0 + 2) * Hd + g];
        float d = Wa1[(size_t)(k0 + 3) * Hd + g];
        uint2 h;
        h.x = pkh(a, b); h.y = pkh(c, d);
        ((uint2*)g_bs16)[(size_t)g * 128 + t] = h;
    }
}

// ============================================================================
// Pipelined single-term fp16 mainloop: block 128(M) x 128(N), K=512 in 64-chunks.
// Stage: A 16K | B 16K = 32 KB; 2 stages. 256 threads, warps 2(M) x 4(N),
// warp tile 64x32, fp32 accumulate. 2 CTAs/SM.
// ============================================================================
#define STG   32768
#define DSMEM (2 * STG + 128)

__device__ __forceinline__ void hmma_loop1(
    const __half* __restrict__ A16, const __half* __restrict__ B16,
    uint32_t smu, float acc[4][4][4])
{
    const int tid = threadIdx.x;
    const int lid = tid & 31, wid = tid >> 5;
    const int wm = wid >> 2, wn = wid & 3;

    int rowS[4], c8S[4];
    uint32_t soS[4];
#pragma unroll
    for (int i = 0; i < 4; i++) {
        int id = tid + 256 * i;
        rowS[i] = id >> 3; c8S[i] = id & 7;
        soS[i] = sw(rowS[i], c8S[i]);
    }

    const int rowA_base = wm * 64 + (lid & 15);
    const int c8A_half = lid >> 4;
    const int rowB_base = wn * 32 + ((lid >> 4) << 3) + (lid & 7);
    const int c8B_half = (lid >> 3) & 1;

    // prefetch chunk 0
    {
        const uint32_t b0 = smu;
#pragma unroll
        for (int i = 0; i < 4; i++) {
            const size_t go = (size_t)rowS[i] * Hd + c8S[i] * 8;
            cp16(b0 + soS[i], A16 + go);
            cp16(b0 + 16384 + soS[i], B16 + go);
        }
        asm volatile("cp.async.commit_group;");
    }

    for (int it = 0; it < 8; ++it) {
        const int s = it & 1;
        if (it < 7) {
            const uint32_t b1 = smu + (s ^ 1) * STG;
            const int kk = (it + 1) * 64;
#pragma unroll
            for (int i = 0; i < 4; i++) {
                const size_t go = (size_t)rowS[i] * Hd + kk + c8S[i] * 8;
                cp16(b1 + soS[i], A16 + go);
                cp16(b1 + 16384 + soS[i], B16 + go);
            }
            asm volatile("cp.async.commit_group;");
            asm volatile("cp.async.wait_group 1;" ::: "memory");
        } else {
            asm volatile("cp.async.wait_group 0;" ::: "memory");
        }
        __syncthreads();

        const uint32_t b0 = smu + s * STG;
#pragma unroll
        for (int ks = 0; ks < 4; ks++) {
            uint32_t bh[8];
#pragma unroll
            for (int q = 0; q < 2; q++) {
                uint32_t off = sw(rowB_base + q * 16, ks * 2 + c8B_half);
                ldsm4(&bh[q * 4], b0 + 16384 + off);
            }
#pragma unroll
            for (int mf = 0; mf < 4; mf++) {
                uint32_t off = sw(rowA_base + mf * 16, ks * 2 + c8A_half);
                uint32_t a16[4];
                ldsm4(a16, b0 + off);
#pragma unroll
                for (int nf = 0; nf < 4; nf++)
                    mma_h(acc[mf][nf], a16, &bh[nf * 2]);
            }
        }
        __syncthreads();
    }
}

// ============================================================================
// k_scores_mma: pre = x@Wa1 (+ba1); partial scores = sum_g tanh(pre)*wa2
// grid (256, 4), 256 threads
// ============================================================================
__global__ __launch_bounds__(256, 2) void k_scores_mma(
    const float* __restrict__ ba1, const float* __restrict__ wa2)
{
    extern __shared__ char dyn[];
    const uint32_t smu = (smem_u32(dyn) + 127) & ~127u;

    const int row0 = blockIdx.x * 128;
    const int gg = blockIdx.y * 128;
    const int tid = threadIdx.x;
    const int lid = tid & 31, wid = tid >> 5;
    const int wm = wid >> 2, wn = wid & 3;
    const int groupID = lid >> 2, tig = lid & 3;

    float acc[4][4][4];
#pragma unroll
    for (int a = 0; a < 4; a++)
#pragma unroll
        for (int b = 0; b < 4; b++)
#pragma unroll
            for (int c = 0; c < 4; c++) acc[a][b][c] = 0.f;

    hmma_loop1(g_x16 + ((size_t)row0 << 9), g_bs16 + ((size_t)gg << 9), smu, acc);

    const int colw = gg + wn * 32;
#pragma unroll
    for (int mf = 0; mf < 4; mf++) {
#pragma unroll
        for (int half = 0; half < 2; half++) {
            const int R = row0 + wm * 64 + mf * 16 + groupID + half * 8;
            float s = 0.f;
#pragma unroll
            for (int nf = 0; nf < 4; nf++) {
                const int g = colw + nf * 8 + tig * 2;
                float a0 = acc[mf][nf][half * 2 + 0];
                float a1 = acc[mf][nf][half * 2 + 1];
                s += ftanh(a0 + __ldg(ba1 + g))     * __ldg(wa2 + g);
                s += ftanh(a1 + __ldg(ba1 + g + 1)) * __ldg(wa2 + g + 1);
            }
            s += __shfl_xor_sync(0xffffffffu, s, 1);
            s += __shfl_xor_sync(0xffffffffu, s, 2);
            if (tig == 0)
                g_spart[(blockIdx.y * 4 + wn) * ROWS_X + R] = s;
        }
    }
}

// ============================================================================
// k_main_mma: pre = y@Wy^T + ci ; out = y + i_x*sigmoid(pre)
// grid (508, 4), 256 threads
// ============================================================================
__global__ __launch_bounds__(256, 2) void k_main_mma(
    const float* __restrict__ y, float* __restrict__ out)
{
    extern __shared__ char dyn[];
    const uint32_t smu = (smem_u32(dyn) + 127) & ~127u;

    const int row0 = blockIdx.x * 128;
    const int gg = blockIdx.y * 128;
    const int tid = threadIdx.x;
    const int lid = tid & 31, wid = tid >> 5;
    const int wm = wid >> 2, wn = wid & 3;
    const int groupID = lid >> 2, tig = lid & 3;

    float acc[4][4][4];
#pragma unroll
    for (int a = 0; a < 4; a++)
#pragma unroll
        for (int b = 0; b < 4; b++)
#pragma unroll
            for (int c = 0; c < 4; c++) acc[a][b][c] = 0.f;

    hmma_loop1(g_y16 + ((size_t)row0 << 9), g_bm16 + ((size_t)gg << 9), smu, acc);

    const int colw = gg + wn * 32;
#pragma unroll
    for (int mf = 0; mf < 4; mf++) {
#pragma unroll
        for (int half = 0; half < 2; half++) {
            const int R = row0 + wm * 64 + mf * 16 + groupID + half * 8;
            const int b = R / 8128;
            const int rem = R - b * 8128;
            const int sp = rem >> 6, n = rem & 63;
            const size_t ybase = ((((size_t)(b * Sn) + sp + 1) * Nn + n) << 9) + colw;
            const float* cib = g_ci + (((size_t)(b * 127 + sp)) << 9) + colw;
            const float* ixb = g_pooled + (((size_t)(b * Sn) + sp) << 9) + colw;
#pragma unroll
            for (int nf = 0; nf < 4; nf++) {
                const int c = nf * 8 + tig * 2;
                float a0 = acc[mf][nf][half * 2 + 0];
                float a1 = acc[mf][nf][half * 2 + 1];
                float2 ci2 = *(const float2*)(cib + c);
                float2 ix2 = *(const float2*)(ixb + c);
                float2 y2  = *(const float2*)(y + ybase + c);
                float2 o;
                o.x = y2.x + ix2.x * fsig(a0 + ci2.x);
                o.y = y2.y + ix2.y * fsig(a1 + ci2.y);
                *(float2*)(out + ybase + c) = o;
            }
        }
    }
}

// ============================================================================
// k_ci_mma: ci = pooled @ Wi^T + bl      (HMMA, pooled fp16)
// A rows = b*128+s (1024 rows, s=127 rows unused). grid (8, 4), 256 threads.
// ============================================================================
__global__ __launch_bounds__(256, 2) void k_ci_mma(const float* __restrict__ bl)
{
    extern __shared__ char dyn[];
    const uint32_t smu = (smem_u32(dyn) + 127) & ~127u;

    const int row0 = blockIdx.x * 128;
    const int gg = blockIdx.y * 128;
    const int tid = threadIdx.x;
    const int lid = tid & 31, wid = tid >> 5;
    const int wm = wid >> 2, wn = wid & 3;
    const int groupID = lid >> 2, tig = lid & 3;

    float acc[4][4][4];
#pragma unroll
    for (int a = 0; a < 4; a++)
#pragma unroll
        for (int b = 0; b < 4; b++)
#pragma unroll
            for (int c = 0; c < 4; c++) acc[a][b][c] = 0.f;

    hmma_loop1(g_p16 + ((size_t)row0 << 9), g_bi16 + ((size_t)gg << 9), smu, acc);

    const int colw = gg + wn * 32;
#pragma unroll
    for (int mf = 0; mf < 4; mf++) {
#pragma unroll
        for (int half = 0; half < 2; half++) {
            const int R = row0 + wm * 64 + mf * 16 + groupID + half * 8;
            const int b = R >> 7, sp = R & 127;
            if (sp < 127) {
                float* crow = g_ci + (((size_t)(b * 127 + sp)) << 9) + colw;
#pragma unroll
                for (int nf = 0; nf < 4; nf++) {
                    const int c = nf * 8 + tig * 2;
                    float2 o;
                    o.x = acc[mf][nf][half * 2 + 0] + __ldg(bl + colw + c);
                    o.y = acc[mf][nf][half * 2 + 1] + __ldg(bl + colw + c + 1);
                    *(float2*)(crow + c) = o;
                }
            }
        }
    }
}

// ============================================================================
// k_pool: softmax over m + weighted pool; writes fp32 + fp16 pooled
// ============================================================================
__global__ __launch_bounds__(256) void k_pool(const float* __restrict__ x)
{
    const int bs = blockIdx.x;
    __shared__ float attn[32];
    const int tid = threadIdx.x;
    if (tid < 32) {
        float s = 0.f;
#pragma unroll
        for (int q = 0; q < NSLICE; q++) s += g_spart[q * ROWS_X + bs * Mn + tid];
        float mx = s;
#pragma unroll
        for (int o = 16; o > 0; o >>= 1)
            mx = fmaxf(mx, __shfl_xor_sync(0xffffffffu, mx, o));
        float e = expf(s - mx);
        float sum = e;
#pragma unroll
        for (int o = 16; o > 0; o >>= 1)
            sum += __shfl_xor_sync(0xffffffffu, sum, o);
        attn[tid] = e / sum;
    }
    __syncthreads();
    const float* xb = x + (size_t)bs * Mn * Hd;
    for (int h = tid * 2; h < Hd; h += 512) {
        float s0 = 0.f, s1 = 0.f;
#pragma unroll
        for (int m = 0; m < Mn; m++) {
            float2 v = *(const float2*)(xb + (size_t)m * Hd + h);
            s0 = fmaf(attn[m], v.x, s0);
            s1 = fmaf(attn[m], v.y, s1);
        }
        *(float2*)(g_pooled + (size_t)bs * Hd + h) = make_float2(s0, s1);
        *(uint32_t*)((__half*)g_p16 + (size_t)bs * Hd + h) = pkh(s0, s1);
    }
}

// ============================================================================
// k_copy0: out[:, 0] = y[:, 0]
// ============================================================================
__global__ __launch_bounds__(256) void k_copy0(
    const float* __restrict__ y, float* __restrict__ out)
{
    const int b = blockIdx.y;
    const int i = (blockIdx.x * 256 + threadIdx.x) * 4;
    const size_t base = (size_t)b * Sn * Nn * Hd;
    if (i < Nn * Hd)
        *(float4*)(out + base + i) = *(const float4*)(y + base + i);
}

extern "C" void kernel_launch(void* const* d_in, const int* in_sizes, int n_in,
                              void* d_out, int out_size)
{
    const float* x   = (const float*)d_in[0];
    const float* y   = (const float*)d_in[1];
    const float* Wa1 = (const float*)d_in[2];
    const float* ba1 = (const float*)d_in[3];
    const float* wa2 = (const float*)d_in[4];
    const float* Wl  = (const float*)d_in[5];
    const float* bl  = (const float*)d_in[6];
    float* out = (float*)d_out;

    cudaFuncSetAttribute(k_scores_mma, cudaFuncAttributeMaxDynamicSharedMemorySize, DSMEM);
    cudaFuncSetAttribute(k_main_mma,   cudaFuncAttributeMaxDynamicSharedMemorySize, DSMEM);
    cudaFuncSetAttribute(k_ci_mma,     cudaFuncAttributeMaxDynamicSharedMemorySize, DSMEM);

    k_cvt_w<<<Hd, 128>>>(Wa1, Wl);
    k_cvt_x<<<ROWS_X, 128>>>(x);
    k_cvt_y<<<ROWS_Y, 128>>>(y);
    k_scores_mma<<<dim3(ROWS_X / 128, 4), 256, DSMEM>>>(ba1, wa2);
    k_pool<<<Bn * Sn, 256>>>(x);
    k_ci_mma<<<dim3(8, 4), 256, DSMEM>>>(bl);
    k_main_mma<<<dim3(ROWS_Y / 128, 4), 256, DSMEM>>>(y, out);
    k_copy0<<<dim3((Nn * Hd / 4 + 255) / 256, Bn), 256>>>(y, out);
}

// round 8
// speedup vs baseline: 5.5301x; 1.0550x over previous
#include <cuda_runtime.h>
#include <cuda_fp16.h>
#include <cstdint>

#define Hd 512
#define Bn 8
#define Sn 128
#define Mn 32
#define Nn 64

#define ROWS_Y  (Bn * (Sn - 1) * Nn)   // 65024 = 508*128
#define ROWS_X  (Bn * Sn * Mn)         // 32768 = 256*128
#define NSLICE  16

// ---------------- device scratch ----------------
__device__ float g_spart[NSLICE * ROWS_X];
__device__ float g_pooled[Bn * Sn * Hd];
__device__ float g_ci[Bn * (Sn - 1) * Hd];

__device__ __half g_x16[(size_t)ROWS_X * Hd];
__device__ __half g_y16[(size_t)ROWS_Y * Hd];
__device__ __half g_p16[(size_t)(Bn * Sn) * Hd];   // pooled fp16, row = b*128+s
__device__ __half g_bs16[Hd * Hd];   // scores B: fp16(Wa1^T) [g][k]
__device__ __half g_bm16[Hd * Hd];   // main B: fp16(Wy rows) [g][k]
__device__ __half g_bi16[Hd * Hd];   // ci B: fp16(Wi rows) [g][k]

// ---------------- helpers ----------------
__device__ __forceinline__ uint32_t smem_u32(const void* p) {
    uint32_t a;
    asm("{ .reg .u64 t; cvta.to.shared.u64 t, %1; cvt.u32.u64 %0, t; }" : "=r"(a) : "l"(p));
    return a;
}
__device__ __forceinline__ void cp16(uint32_t saddr, const void* gptr) {
    asm volatile("cp.async.cg.shared.global [%0], [%1], 16;" :: "r"(saddr), "l"(gptr));
}
__device__ __forceinline__ void ldsm4(uint32_t* r, uint32_t addr) {
    asm volatile("ldmatrix.sync.aligned.m8n8.x4.shared.b16 {%0,%1,%2,%3}, [%4];"
                 : "=r"(r[0]), "=r"(r[1]), "=r"(r[2]), "=r"(r[3]) : "r"(addr));
}
__device__ __forceinline__ void mma_h(float* c, const uint32_t* a, const uint32_t* b) {
    asm volatile(
        "mma.sync.aligned.m16n8k16.row.col.f32.f16.f16.f32 "
        "{%0,%1,%2,%3}, {%4,%5,%6,%7}, {%8,%9}, {%0,%1,%2,%3};"
        : "+f"(c[0]), "+f"(c[1]), "+f"(c[2]), "+f"(c[3])
        : "r"(a[0]), "r"(a[1]), "r"(a[2]), "r"(a[3]), "r"(b[0]), "r"(b[1]));
}
__device__ __forceinline__ float tanh_fast(float x) {
    float r;
    asm("tanh.approx.f32 %0, %1;" : "=f"(r) : "f"(x));
    return r;
}
// gate = sigmoid(x) = 0.5 + 0.5*tanh(0.5x)  (1 MUFU)
__device__ __forceinline__ float fsig(float x) {
    return fmaf(tanh_fast(0.5f * x), 0.5f, 0.5f);
}

__device__ __forceinline__ unsigned pkh(float a, float b) {
    __half2 t = __floats2half2_rn(a, b);
    return *reinterpret_cast<unsigned*>(&t);
}

// swizzled offset inside a [rows x 64 fp16] tile (128 B rows)
__device__ __forceinline__ uint32_t sw(int row, int c8) {
    return (uint32_t)(row * 128 + ((c8 ^ (row & 7)) << 4));
}

// ============================================================================
// Conversion kernels (fp16 only)
// ============================================================================
__global__ __launch_bounds__(128) void k_cvt_x(const float* __restrict__ x) {
    const int r = blockIdx.x;
    const int t = threadIdx.x;
    float4 v = *(const float4*)(x + ((size_t)r << 9) + t * 4);
    uint2 h;
    h.x = pkh(v.x, v.y); h.y = pkh(v.z, v.w);
    ((uint2*)g_x16)[(size_t)r * 128 + t] = h;
}

// blocks [0, 65024): convert y rows; blocks [65024, 65536): out[:,0] = y[:,0]
__global__ __launch_bounds__(128) void k_cvt_y(const float* __restrict__ y,
                                               float* __restrict__ out) {
    const int r = blockIdx.x;
    const int t = threadIdx.x;
    if (r < ROWS_Y / Nn * Nn /* 65024 */) {
        const int b = r / (127 * Nn);
        const int rem = r - b * (127 * Nn);
        const int sp = rem >> 6, n = rem & 63;
        const float* src = y + ((((size_t)(b * Sn) + sp + 1) * Nn + n) << 9) + t * 4;
        float4 v = *(const float4*)src;
        uint2 h;
        h.x = pkh(v.x, v.y); h.y = pkh(v.z, v.w);
        ((uint2*)g_y16)[(size_t)r * 128 + t] = h;
    } else {
        const int i = (r - 65024) * 128 + t;     // [0, 65536) float4 slots
        const int b = i >> 13, j = i & 8191;
        const size_t off = (size_t)b * Sn * Nn * Hd + (size_t)j * 4;
        *(float4*)(out + off) = *(const float4*)(y + off);
    }
}

__global__ __launch_bounds__(128) void k_cvt_w(const float* __restrict__ Wa1,
                                               const float* __restrict__ Wl) {
    const int g = blockIdx.x;
    const int t = threadIdx.x;
    {   // main B: Wl row g, first Hd cols (Wy)
        float4 v = *(const float4*)(Wl + (size_t)g * 1024 + t * 4);
        uint2 h;
        h.x = pkh(v.x, v.y); h.y = pkh(v.z, v.w);
        ((uint2*)g_bm16)[(size_t)g * 128 + t] = h;
    }
    {   // ci B: Wl row g, cols [Hd, 2Hd) (Wi)
        float4 v = *(const float4*)(Wl + (size_t)g * 1024 + Hd + t * 4);
        uint2 h;
        h.x = pkh(v.x, v.y); h.y = pkh(v.z, v.w);
        ((uint2*)g_bi16)[(size_t)g * 128 + t] = h;
    }
    {   // scores B: Wa1^T row g
        int k0 = t * 4;
        float a = Wa1[(size_t)(k0 + 0) * Hd + g];
        float b = Wa1[(size_t)(k0 + 1) * Hd + g];
        float c = Wa1[(size_t)(k0 + 2) * Hd + g];
        float d = Wa1[(size_t)(k0 + 3) * Hd + g];
        uint2 h;
        h.x = pkh(a, b); h.y = pkh(c, d);
        ((uint2*)g_bs16)[(size_t)g * 128 + t] = h;
    }
}

// ============================================================================
// 3-stage pipelined fp16 mainloop: block 128(M) x 128(N), K=512 in 64-chunks.
// Stage: A 16K | B 16K = 32 KB; 3 stages (96 KB/CTA), 2 CTAs/SM.
// 256 threads, warps 2(M) x 4(N), warp tile 64x32, fp32 accumulate.
// ONE __syncthreads per chunk; prefetch issued before compute.
// ============================================================================
#define STG   32768
#define DSMEM (3 * STG + 128)

__device__ __forceinline__ void hmma_loop3(
    const __half* __restrict__ A16, const __half* __restrict__ B16,
    uint32_t smu, float acc[4][4][4])
{
    const int tid = threadIdx.x;
    const int lid = tid & 31, wid = tid >> 5;
    const int wm = wid >> 2, wn = wid & 3;

    int rowS[4], c8S[4];
    uint32_t soS[4];
#pragma unroll
    for (int i = 0; i < 4; i++) {
        int id = tid + 256 * i;
        rowS[i] = id >> 3; c8S[i] = id & 7;
        soS[i] = sw(rowS[i], c8S[i]);
    }

    const int rowA_base = wm * 64 + (lid & 15);
    const int c8A_half = lid >> 4;
    const int rowB_base = wn * 32 + ((lid >> 4) << 3) + (lid & 7);
    const int c8B_half = (lid >> 3) & 1;

    // prologue: chunks 0 and 1
#pragma unroll
    for (int p = 0; p < 2; p++) {
        const uint32_t bb = smu + p * STG;
        const int kk = p * 64;
#pragma unroll
        for (int i = 0; i < 4; i++) {
            const size_t go = (size_t)rowS[i] * Hd + kk + c8S[i] * 8;
            cp16(bb + soS[i], A16 + go);
            cp16(bb + 16384 + soS[i], B16 + go);
        }
        asm volatile("cp.async.commit_group;");
    }

#pragma unroll
    for (int it = 0; it < 8; ++it) {
        if (it == 7) asm volatile("cp.async.wait_group 0;" ::: "memory");
        else         asm volatile("cp.async.wait_group 1;" ::: "memory");
        __syncthreads();

        // issue chunk it+2 into stage (it+2)%3 (drained: == (it-1)%3)
        if (it < 6) {
            const uint32_t bb = smu + ((it + 2) % 3) * STG;
            const int kk = (it + 2) * 64;
#pragma unroll
            for (int i = 0; i < 4; i++) {
                const size_t go = (size_t)rowS[i] * Hd + kk + c8S[i] * 8;
                cp16(bb + soS[i], A16 + go);
                cp16(bb + 16384 + soS[i], B16 + go);
            }
            asm volatile("cp.async.commit_group;");
        }

        const uint32_t b0 = smu + (it % 3) * STG;
#pragma unroll
        for (int ks = 0; ks < 4; ks++) {
            uint32_t bh[8];
#pragma unroll
            for (int q = 0; q < 2; q++) {
                uint32_t off = sw(rowB_base + q * 16, ks * 2 + c8B_half);
                ldsm4(&bh[q * 4], b0 + 16384 + off);
            }
#pragma unroll
            for (int mf = 0; mf < 4; mf++) {
                uint32_t off = sw(rowA_base + mf * 16, ks * 2 + c8A_half);
                uint32_t a16[4];
                ldsm4(a16, b0 + off);
#pragma unroll
                for (int nf = 0; nf < 4; nf++)
                    mma_h(acc[mf][nf], a16, &bh[nf * 2]);
            }
        }
    }
}

// ============================================================================
// k_scores_mma: pre = x@Wa1 (+ba1); partial scores = sum_g tanh(pre)*wa2
// grid (256, 4), 256 threads
// ============================================================================
__global__ __launch_bounds__(256, 2) void k_scores_mma(
    const float* __restrict__ ba1, const float* __restrict__ wa2)
{
    extern __shared__ char dyn[];
    const uint32_t smu = (smem_u32(dyn) + 127) & ~127u;

    const int row0 = blockIdx.x * 128;
    const int gg = blockIdx.y * 128;
    const int tid = threadIdx.x;
    const int lid = tid & 31, wid = tid >> 5;
    const int wm = wid >> 2, wn = wid & 3;
    const int groupID = lid >> 2, tig = lid & 3;

    float acc[4][4][4];
#pragma unroll
    for (int a = 0; a < 4; a++)
#pragma unroll
        for (int b = 0; b < 4; b++)
#pragma unroll
            for (int c = 0; c < 4; c++) acc[a][b][c] = 0.f;

    hmma_loop3(g_x16 + ((size_t)row0 << 9), g_bs16 + ((size_t)gg << 9), smu, acc);

    const int colw = gg + wn * 32;
#pragma unroll
    for (int mf = 0; mf < 4; mf++) {
#pragma unroll
        for (int half = 0; half < 2; half++) {
            const int R = row0 + wm * 64 + mf * 16 + groupID + half * 8;
            float s = 0.f;
#pragma unroll
            for (int nf = 0; nf < 4; nf++) {
                const int g = colw + nf * 8 + tig * 2;
                float a0 = acc[mf][nf][half * 2 + 0];
                float a1 = acc[mf][nf][half * 2 + 1];
                s += tanh_fast(a0 + __ldg(ba1 + g))     * __ldg(wa2 + g);
                s += tanh_fast(a1 + __ldg(ba1 + g + 1)) * __ldg(wa2 + g + 1);
            }
            s += __shfl_xor_sync(0xffffffffu, s, 1);
            s += __shfl_xor_sync(0xffffffffu, s, 2);
            if (tig == 0)
                g_spart[(blockIdx.y * 4 + wn) * ROWS_X + R] = s;
        }
    }
}

// ============================================================================
// k_main_mma: pre = y@Wy^T + ci ; out = y + i_x*sigmoid(pre)
// grid (508, 4), 256 threads
// ============================================================================
__global__ __launch_bounds__(256, 2) void k_main_mma(
    const float* __restrict__ y, float* __restrict__ out)
{
    extern __shared__ char dyn[];
    const uint32_t smu = (smem_u32(dyn) + 127) & ~127u;

    const int row0 = blockIdx.x * 128;
    const int gg = blockIdx.y * 128;
    const int tid = threadIdx.x;
    const int lid = tid & 31, wid = tid >> 5;
    const int wm = wid >> 2, wn = wid & 3;
    const int groupID = lid >> 2, tig = lid & 3;

    float acc[4][4][4];
#pragma unroll
    for (int a = 0; a < 4; a++)
#pragma unroll
        for (int b = 0; b < 4; b++)
#pragma unroll
            for (int c = 0; c < 4; c++) acc[a][b][c] = 0.f;

    hmma_loop3(g_y16 + ((size_t)row0 << 9), g_bm16 + ((size_t)gg << 9), smu, acc);

    const int colw = gg + wn * 32;
#pragma unroll
    for (int mf = 0; mf < 4; mf++) {
#pragma unroll
        for (int half = 0; half < 2; half++) {
            const int R = row0 + wm * 64 + mf * 16 + groupID + half * 8;
            const int b = R / 8128;
            const int rem = R - b * 8128;
            const int sp = rem >> 6, n = rem & 63;
            const size_t ybase = ((((size_t)(b * Sn) + sp + 1) * Nn + n) << 9) + colw;
            const float* cib = g_ci + (((size_t)(b * 127 + sp)) << 9) + colw;
            const float* ixb = g_pooled + (((size_t)(b * Sn) + sp) << 9) + colw;
#pragma unroll
            for (int nf = 0; nf < 4; nf++) {
                const int c = nf * 8 + tig * 2;
                float a0 = acc[mf][nf][half * 2 + 0];
                float a1 = acc[mf][nf][half * 2 + 1];
                float2 ci2 = *(const float2*)(cib + c);
                float2 ix2 = *(const float2*)(ixb + c);
                float2 y2  = *(const float2*)(y + ybase + c);
                float2 o;
                o.x = y2.x + ix2.x * fsig(a0 + ci2.x);
                o.y = y2.y + ix2.y * fsig(a1 + ci2.y);
                *(float2*)(out + ybase + c) = o;
            }
        }
    }
}

// ============================================================================
// k_ci_mma: ci = pooled @ Wi^T + bl      (HMMA, pooled fp16)
// A rows = b*128+s (1024 rows, s=127 rows unused). grid (8, 4), 256 threads.
// ============================================================================
__global__ __launch_bounds__(256, 2) void k_ci_mma(const float* __restrict__ bl)
{
    extern __shared__ char dyn[];
    const uint32_t smu = (smem_u32(dyn) + 127) & ~127u;

    const int row0 = blockIdx.x * 128;
    const int gg = blockIdx.y * 128;
    const int tid = threadIdx.x;
    const int lid = tid & 31, wid = tid >> 5;
    const int wm = wid >> 2, wn = wid & 3;
    const int groupID = lid >> 2, tig = lid & 3;

    float acc[4][4][4];
#pragma unroll
    for (int a = 0; a < 4; a++)
#pragma unroll
        for (int b = 0; b < 4; b++)
#pragma unroll
            for (int c = 0; c < 4; c++) acc[a][b][c] = 0.f;

    hmma_loop3(g_p16 + ((size_t)row0 << 9), g_bi16 + ((size_t)gg << 9), smu, acc);

    const int colw = gg + wn * 32;
#pragma unroll
    for (int mf = 0; mf < 4; mf++) {
#pragma unroll
        for (int half = 0; half < 2; half++) {
            const int R = row0 + wm * 64 + mf * 16 + groupID + half * 8;
            const int b = R >> 7, sp = R & 127;
            if (sp < 127) {
                float* crow = g_ci + (((size_t)(b * 127 + sp)) << 9) + colw;
#pragma unroll
                for (int nf = 0; nf < 4; nf++) {
                    const int c = nf * 8 + tig * 2;
                    float2 o;
                    o.x = acc[mf][nf][half * 2 + 0] + __ldg(bl + colw + c);
                    o.y = acc[mf][nf][half * 2 + 1] + __ldg(bl + colw + c + 1);
                    *(float2*)(crow + c) = o;
                }
            }
        }
    }
}

// ============================================================================
// k_pool: softmax over m + weighted pool; writes fp32 + fp16 pooled
// ============================================================================
__global__ __launch_bounds__(256) void k_pool(const float* __restrict__ x)
{
    const int bs = blockIdx.x;
    __shared__ float attn[32];
    const int tid = threadIdx.x;
    if (tid < 32) {
        float s = 0.f;
#pragma unroll
        for (int q = 0; q < NSLICE; q++) s += g_spart[q * ROWS_X + bs * Mn + tid];
        float mx = s;
#pragma unroll
        for (int o = 16; o > 0; o >>= 1)
            mx = fmaxf(mx, __shfl_xor_sync(0xffffffffu, mx, o));
        float e = expf(s - mx);
        float sum = e;
#pragma unroll
        for (int o = 16; o > 0; o >>= 1)
            sum += __shfl_xor_sync(0xffffffffu, sum, o);
        attn[tid] = e / sum;
    }
    __syncthreads();
    const float* xb = x + (size_t)bs * Mn * Hd;
    for (int h = tid * 2; h < Hd; h += 512) {
        float s0 = 0.f, s1 = 0.f;
#pragma unroll
        for (int m = 0; m < Mn; m++) {
            float2 v = *(const float2*)(xb + (size_t)m * Hd + h);
            s0 = fmaf(attn[m], v.x, s0);
            s1 = fmaf(attn[m], v.y, s1);
        }
        *(float2*)(g_pooled + (size_t)bs * Hd + h) = make_float2(s0, s1);
        *(uint32_t*)((__half*)g_p16 + (size_t)bs * Hd + h) = pkh(s0, s1);
    }
}

extern "C" void kernel_launch(void* const* d_in, const int* in_sizes, int n_in,
                              void* d_out, int out_size)
{
    const float* x   = (const float*)d_in[0];
    const float* y   = (const float*)d_in[1];
    const float* Wa1 = (const float*)d_in[2];
    const float* ba1 = (const float*)d_in[3];
    const float* wa2 = (const float*)d_in[4];
    const float* Wl  = (const float*)d_in[5];
    const float* bl  = (const float*)d_in[6];
    float* out = (float*)d_out;

    cudaFuncSetAttribute(k_scores_mma, cudaFuncAttributeMaxDynamicSharedMemorySize, DSMEM);
    cudaFuncSetAttribute(k_main_mma,   cudaFuncAttributeMaxDynamicSharedMemorySize, DSMEM);
    cudaFuncSetAttribute(k_ci_mma,     cudaFuncAttributeMaxDynamicSharedMemorySize, DSMEM);

    k_cvt_w<<<Hd, 128>>>(Wa1, Wl);
    k_cvt_x<<<ROWS_X, 128>>>(x);
    k_cvt_y<<<65536, 128>>>(y, out);
    k_scores_mma<<<dim3(ROWS_X / 128, 4), 256, DSMEM>>>(ba1, wa2);
    k_pool<<<Bn * Sn, 256>>>(x);
    k_ci_mma<<<dim3(8, 4), 256, DSMEM>>>(bl);
    k_main_mma<<<dim3(ROWS_Y / 128, 4), 256, DSMEM>>>(y, out);
}